// round 7
// baseline (speedup 1.0000x reference)
#include <cuda_runtime.h>
#include <math.h>
#include <stdint.h>

#define S_LEN 2048
#define HDIM  2048
#define NB    2
#define NH    16
#define DH    128
#define MROWS (NB * S_LEN)   // 4096

__device__ float g_Q[MROWS * HDIM];
__device__ float g_K[MROWS * HDIM];
__device__ float g_V[MROWS * HDIM];
__device__ float g_C[MROWS * HDIM];
__device__ float g_X[MROWS * HDIM];          // tf32-rounded X
__device__ float g_Wq[HDIM * HDIM];          // tf32-rounded, pre-scaled 1/sqrt(dh)
__device__ float g_Wk[HDIM * HDIM];
__device__ float g_Wv[HDIM * HDIM];
__device__ float g_Wo[HDIM * HDIM];

// ---------------------------------------------------------------------------
// TF32 helpers
// ---------------------------------------------------------------------------
__device__ __forceinline__ float f2tf32(float x)
{
    unsigned u;
    asm("cvt.rna.tf32.f32 %0, %1;" : "=r"(u) : "f"(x));
    return __uint_as_float(u);
}

__device__ __forceinline__ void mma_tf32(float* c, uint2 alo, uint2 ahi, uint2 b)
{
    asm("mma.sync.aligned.m16n8k8.row.col.f32.tf32.tf32.f32 "
        "{%0,%1,%2,%3}, {%4,%5,%6,%7}, {%8,%9}, {%0,%1,%2,%3};"
        : "+f"(c[0]), "+f"(c[1]), "+f"(c[2]), "+f"(c[3])
        : "r"(alo.x), "r"(ahi.x), "r"(alo.y), "r"(ahi.y),
          "r"(b.x),  "r"(b.y));
}

__device__ __forceinline__ void mma_tf32_r(float* c, float a0, float a1,
                                           float a2, float a3,
                                           float b0, float b1)
{
    asm("mma.sync.aligned.m16n8k8.row.col.f32.tf32.tf32.f32 "
        "{%0,%1,%2,%3}, {%4,%5,%6,%7}, {%8,%9}, {%0,%1,%2,%3};"
        : "+f"(c[0]), "+f"(c[1]), "+f"(c[2]), "+f"(c[3])
        : "r"(__float_as_uint(a0)), "r"(__float_as_uint(a1)),
          "r"(__float_as_uint(a2)), "r"(__float_as_uint(a3)),
          "r"(__float_as_uint(b0)), "r"(__float_as_uint(b1)));
}

__device__ __forceinline__ void cp_async16(uint32_t saddr, const float* g)
{
    asm volatile("cp.async.cg.shared.global [%0], [%1], 16;"
                 :: "r"(saddr), "l"(g));
}
#define CP_COMMIT() asm volatile("cp.async.commit_group;")
#define CP_WAIT(N)  asm volatile("cp.async.wait_group %0;" :: "n"(N))

// ---------------------------------------------------------------------------
// tf32 pre-rounding copy kernel (optionally scaled)
// ---------------------------------------------------------------------------
__global__ void cvt_tf32_kernel(const float* __restrict__ src,
                                float* __restrict__ dst,
                                int n4, float scale)
{
    int i = blockIdx.x * 256 + threadIdx.x;
    if (i >= n4) return;
    float4 v = ((const float4*)src)[i];
    v.x = f2tf32(v.x * scale);
    v.y = f2tf32(v.y * scale);
    v.z = f2tf32(v.z * scale);
    v.w = f2tf32(v.w * scale);
    ((float4*)dst)[i] = v;
}

// ---------------------------------------------------------------------------
// GEMM v4: C[M,2048] = A[M,2048] @ B[2048,2048]^T (+bias).
// CTA 128x256, 256 threads = 8 warps (2m x 4n), warp tile 64x64, BK=32.
// 3-stage cp.async pipeline (144 KB), register double-buffered fragments.
// Smem: [row][8 float4-chunks], chunk j at j ^ (row&7). Operands pre-rounded.
// ---------------------------------------------------------------------------
#define GK 2048
#define TILE_AF 4096                 // 128 rows * 32 floats
#define TILE_BF 8192                 // 256 rows * 32 floats
#define GEMM_SMEM_BYTES (3 * (TILE_AF + TILE_BF) * 4)   // 144 KB

template <bool ROUND, bool HASBIAS>
__device__ __forceinline__ void gemm_v4_body(const float* __restrict__ A,
                                             const float* __restrict__ B,
                                             const float* __restrict__ bias,
                                             float* __restrict__ C)
{
    extern __shared__ float smem[];
    float* As = smem;                    // [3][4096]
    float* Bs = smem + 3 * TILE_AF;      // [3][8192]

    const int tid    = threadIdx.x;
    const int lane   = tid & 31;
    const int wid    = tid >> 5;
    const int warp_m = wid >> 2;         // 0..1
    const int warp_n = wid & 3;          // 0..3
    const int g      = lane >> 2;        // 0..7
    const int t      = lane & 3;         // 0..3
    const int bm     = blockIdx.y * 128;
    const int bn     = blockIdx.x * 256;

    // cp.async: thread covers rows (tid>>3) + 32*it, chunk tid&7
    const int tr = tid >> 3;             // 0..31
    const int tc = tid & 7;
    const float* gA = A + (size_t)(bm + tr) * GK + tc * 4;
    const float* gB = B + (size_t)(bn + tr) * GK + tc * 4;
    const int dst0 = tr * 32 + (((tc ^ (tr & 7))) << 2);   // float offset

    uint32_t sA = (uint32_t)__cvta_generic_to_shared(As);
    uint32_t sB = (uint32_t)__cvta_generic_to_shared(Bs);

    auto issue = [&](int stage, int k0) {
        uint32_t da = sA + (stage * TILE_AF + dst0) * 4;
        uint32_t db = sB + (stage * TILE_BF + dst0) * 4;
#pragma unroll
        for (int it = 0; it < 4; it++)
            cp_async16(da + it * 1024 * 4, gA + (size_t)it * 32 * GK + k0);
#pragma unroll
        for (int it = 0; it < 8; it++)
            cp_async16(db + it * 1024 * 4, gB + (size_t)it * 32 * GK + k0);
        CP_COMMIT();
    };

    issue(0, 0);
    issue(1, 32);

    float acc[4][8][4];
#pragma unroll
    for (int mt = 0; mt < 4; mt++)
#pragma unroll
        for (int nt = 0; nt < 8; nt++)
#pragma unroll
            for (int i = 0; i < 4; i++) acc[mt][nt][i] = 0.f;

    int rbA[4], rbB[8];
#pragma unroll
    for (int mt = 0; mt < 4; mt++)
        rbA[mt] = (warp_m * 64 + mt * 16 + g) * 32;
#pragma unroll
    for (int nt = 0; nt < 8; nt++)
        rbB[nt] = (warp_n * 64 + nt * 8 + g) * 32;

    float a[2][4][4], b[2][8][2];

    const int nk = GK / 32;   // 64
    for (int kt = 0; kt < nk; kt++) {
        if (kt < nk - 1) { CP_WAIT(1); } else { CP_WAIT(0); }
        __syncthreads();
        if (kt + 2 < nk) issue((kt + 2) % 3, (kt + 2) * 32);

        const float* as = As + (kt % 3) * TILE_AF;
        const float* bs = Bs + (kt % 3) * TILE_BF;

        // preload k8 = 0 fragments
        {
            const int o0 = ((0 ^ g) << 2) + t;
            const int o1 = ((1 ^ g) << 2) + t;
#pragma unroll
            for (int mt = 0; mt < 4; mt++) {
                a[0][mt][0] = as[rbA[mt] + o0];
                a[0][mt][1] = as[rbA[mt] + 256 + o0];
                a[0][mt][2] = as[rbA[mt] + o1];
                a[0][mt][3] = as[rbA[mt] + 256 + o1];
            }
#pragma unroll
            for (int nt = 0; nt < 8; nt++) {
                b[0][nt][0] = bs[rbB[nt] + o0];
                b[0][nt][1] = bs[rbB[nt] + o1];
            }
        }

#pragma unroll
        for (int k8 = 0; k8 < 4; k8++) {
            const int cur = k8 & 1;
            const int nxt = cur ^ 1;
            if (k8 < 3) {
                const int o0 = (((2 * (k8 + 1))     ^ g) << 2) + t;
                const int o1 = (((2 * (k8 + 1) + 1) ^ g) << 2) + t;
#pragma unroll
                for (int mt = 0; mt < 4; mt++) {
                    a[nxt][mt][0] = as[rbA[mt] + o0];
                    a[nxt][mt][1] = as[rbA[mt] + 256 + o0];
                    a[nxt][mt][2] = as[rbA[mt] + o1];
                    a[nxt][mt][3] = as[rbA[mt] + 256 + o1];
                }
#pragma unroll
                for (int nt = 0; nt < 8; nt++) {
                    b[nxt][nt][0] = bs[rbB[nt] + o0];
                    b[nxt][nt][1] = bs[rbB[nt] + o1];
                }
            }
#pragma unroll
            for (int mt = 0; mt < 4; mt++)
#pragma unroll
                for (int nt = 0; nt < 8; nt++)
                    mma_tf32_r(acc[mt][nt],
                               a[cur][mt][0], a[cur][mt][1],
                               a[cur][mt][2], a[cur][mt][3],
                               b[cur][nt][0], b[cur][nt][1]);
        }
    }

    // Epilogue: c0,c1 at (g, 2t..2t+1); c2,c3 at (g+8, ...)
#pragma unroll
    for (int mt = 0; mt < 4; mt++) {
        int row = bm + warp_m * 64 + mt * 16 + g;
#pragma unroll
        for (int nt = 0; nt < 8; nt++) {
            int col = bn + warp_n * 64 + nt * 8 + 2 * t;
            float b0 = 0.f, b1 = 0.f;
            if (HASBIAS) { b0 = bias[col]; b1 = bias[col + 1]; }
            float v0 = acc[mt][nt][0] + b0, v1 = acc[mt][nt][1] + b1;
            float v2 = acc[mt][nt][2] + b0, v3 = acc[mt][nt][3] + b1;
            if (ROUND) {
                v0 = f2tf32(v0); v1 = f2tf32(v1);
                v2 = f2tf32(v2); v3 = f2tf32(v3);
            }
            *(float2*)(C + (size_t)row * HDIM + col)       = make_float2(v0, v1);
            *(float2*)(C + (size_t)(row + 8) * HDIM + col) = make_float2(v2, v3);
        }
    }
}

__global__ void __launch_bounds__(256, 1) qkv_gemm_kernel()
{
    const float* B = (blockIdx.z == 0) ? g_Wq : (blockIdx.z == 1) ? g_Wk : g_Wv;
    float* C       = (blockIdx.z == 0) ? g_Q  : (blockIdx.z == 1) ? g_K  : g_V;
    gemm_v4_body<true, false>(g_X, B, nullptr, C);
}

__global__ void __launch_bounds__(256, 1) out_gemm_kernel(
    const float* __restrict__ bo, float* __restrict__ out)
{
    gemm_v4_body<false, true>(g_C, g_Wo, bo, out);
}

// ---------------------------------------------------------------------------
// RoPE in-place on g_Q, g_K (writes tf32-rounded)
// ---------------------------------------------------------------------------
__global__ void rope_kernel(const int* __restrict__ pos_ids)
{
    int idx = blockIdx.x * 256 + threadIdx.x;
    if (idx >= MROWS * NH * 64) return;
    int d = idx & 63;
    int h = (idx >> 6) & 15;
    int m = idx >> 10;
    int s = m & (S_LEN - 1);

    float p = (float)pos_ids[s];
    float theta = expf(-0.14391156531392624f * (float)d);
    float ang = p * theta;
    float sn, cs;
    sincosf(ang, &sn, &cs);

    size_t base = (size_t)m * HDIM + h * DH + d;
    float q1 = g_Q[base], q2 = g_Q[base + 64];
    g_Q[base]      = f2tf32(q1 * cs - q2 * sn);
    g_Q[base + 64] = f2tf32(q1 * sn + q2 * cs);
    float k1 = g_K[base], k2 = g_K[base + 64];
    g_K[base]      = f2tf32(k1 * cs - k2 * sn);
    g_K[base + 64] = f2tf32(k1 * sn + k2 * cs);
}

// ---------------------------------------------------------------------------
// TF32 MMA flash attention (unchanged from R5). Sources pre-rounded.
// ---------------------------------------------------------------------------
#define CQ 1034
#define CK 522
#define VSTRIDE 132
#define ATT_SMEM_FLOATS (16 * CQ + 16 * CK + 64 * VSTRIDE)
#define ATT_SMEM_BYTES  (ATT_SMEM_FLOATS * 4)

__global__ void __launch_bounds__(256) attn_kernel()
{
    extern __shared__ float sm[];
    float* Qs = sm;
    float* Ks = Qs + 16 * CQ;
    float* Vs = Ks + 16 * CK;

    const int tid  = threadIdx.x;
    const int lane = tid & 31;
    const int w    = tid >> 5;
    const int g    = lane >> 2;
    const int t    = lane & 3;
    const int qt   = (gridDim.x - 1) - blockIdx.x;
    const int h    = blockIdx.y;
    const int n    = blockIdx.z;
    const int q0   = qt * 128;

    const size_t rowbase = (size_t)n * S_LEN;
    const size_t hoff    = (size_t)h * DH;

#pragma unroll
    for (int it = 0; it < 16; it++) {
        int id = tid + it * 256;
        int r  = id >> 5;
        int f4 = id & 31;
        int so = (f4 >> 1) * CQ + r * 8 + (f4 & 1);
        float4 v = *(const float4*)(g_Q + (rowbase + q0 + r) * HDIM + hoff + f4 * 4);
        Qs[so + 0] = v.x;
        Qs[so + 2] = v.y;
        Qs[so + 4] = v.z;
        Qs[so + 6] = v.w;
    }

    float o[16][4];
#pragma unroll
    for (int dd = 0; dd < 16; dd++)
#pragma unroll
        for (int i = 0; i < 4; i++) o[dd][i] = 0.f;
    float m0 = -1e30f, m1 = -1e30f, l0 = 0.f, l1 = 0.f;

    const int row0 = q0 + w * 16 + g;
    const int nkt  = 2 * (qt + 1);

    for (int kt = 0; kt < nkt; kt++) {
        __syncthreads();
        const int k0 = kt * 64;
#pragma unroll
        for (int it = 0; it < 8; it++) {
            int id = tid + it * 256;
            int r  = id >> 5;
            int f4 = id & 31;
            size_t gg = (rowbase + k0 + r) * HDIM + hoff + f4 * 4;
            float4 vk = *(const float4*)(g_K + gg);
            int so = (f4 >> 1) * CK + r * 8 + (f4 & 1);
            Ks[so + 0] = vk.x;
            Ks[so + 2] = vk.y;
            Ks[so + 4] = vk.z;
            Ks[so + 6] = vk.w;
            *(float4*)&Vs[r * VSTRIDE + f4 * 4] = *(const float4*)(g_V + gg);
        }
        __syncthreads();

        float s[8][4];
#pragma unroll
        for (int nn = 0; nn < 8; nn++)
#pragma unroll
            for (int i = 0; i < 4; i++) s[nn][i] = 0.f;

#pragma unroll
        for (int c = 0; c < 16; c++) {
            const float* qp = &Qs[c * CQ + (w * 16 + g) * 8 + 2 * t];
            uint2 alo = *(const uint2*)qp;
            uint2 ahi = *(const uint2*)(qp + 64);
#pragma unroll
            for (int nn = 0; nn < 8; nn++) {
                uint2 b = *(const uint2*)&Ks[c * CK + (nn * 8 + g) * 8 + 2 * t];
                mma_tf32(s[nn], alo, ahi, b);
            }
        }

        if (k0 + 63 > row0) {
#pragma unroll
            for (int nn = 0; nn < 8; nn++) {
                int col = k0 + nn * 8 + 2 * t;
                if (col > row0)     s[nn][0] = -1e30f;
                if (col + 1 > row0) s[nn][1] = -1e30f;
                if (col > row0 + 8)     s[nn][2] = -1e30f;
                if (col + 1 > row0 + 8) s[nn][3] = -1e30f;
            }
        }

        float mx0 = -1e30f, mx1 = -1e30f;
#pragma unroll
        for (int nn = 0; nn < 8; nn++) {
            mx0 = fmaxf(mx0, fmaxf(s[nn][0], s[nn][1]));
            mx1 = fmaxf(mx1, fmaxf(s[nn][2], s[nn][3]));
        }
        mx0 = fmaxf(mx0, __shfl_xor_sync(0xffffffffu, mx0, 1));
        mx0 = fmaxf(mx0, __shfl_xor_sync(0xffffffffu, mx0, 2));
        mx1 = fmaxf(mx1, __shfl_xor_sync(0xffffffffu, mx1, 1));
        mx1 = fmaxf(mx1, __shfl_xor_sync(0xffffffffu, mx1, 2));

        float newm0 = fmaxf(m0, mx0);
        float newm1 = fmaxf(m1, mx1);
        float alpha0 = __expf(m0 - newm0);
        float alpha1 = __expf(m1 - newm1);
        m0 = newm0; m1 = newm1;

        float sum0 = 0.f, sum1 = 0.f;
#pragma unroll
        for (int nn = 0; nn < 8; nn++) {
            float p0 = f2tf32(__expf(s[nn][0] - newm0));
            float p1 = f2tf32(__expf(s[nn][1] - newm0));
            float p2 = f2tf32(__expf(s[nn][2] - newm1));
            float p3 = f2tf32(__expf(s[nn][3] - newm1));
            s[nn][0] = p0; s[nn][1] = p1; s[nn][2] = p2; s[nn][3] = p3;
            sum0 += p0 + p1;
            sum1 += p2 + p3;
        }
        sum0 += __shfl_xor_sync(0xffffffffu, sum0, 1);
        sum0 += __shfl_xor_sync(0xffffffffu, sum0, 2);
        sum1 += __shfl_xor_sync(0xffffffffu, sum1, 1);
        sum1 += __shfl_xor_sync(0xffffffffu, sum1, 2);
        l0 = l0 * alpha0 + sum0;
        l1 = l1 * alpha1 + sum1;

#pragma unroll
        for (int dd = 0; dd < 16; dd++) {
            o[dd][0] *= alpha0; o[dd][1] *= alpha0;
            o[dd][2] *= alpha1; o[dd][3] *= alpha1;
        }

#pragma unroll
        for (int c8 = 0; c8 < 8; c8++) {
            const float* vp = &Vs[(c8 * 8 + 2 * t) * VSTRIDE + g];
#pragma unroll
            for (int dd = 0; dd < 16; dd++) {
                float b0 = vp[dd * 8];
                float b1 = vp[dd * 8 + VSTRIDE];
                mma_tf32_r(o[dd], s[c8][0], s[c8][2], s[c8][1], s[c8][3], b0, b1);
            }
        }
    }

    float inv0 = 1.f / l0;
    float inv1 = 1.f / l1;
    size_t r0 = (rowbase + row0) * HDIM + hoff;
    size_t r1 = r0 + 8 * HDIM;
#pragma unroll
    for (int dd = 0; dd < 16; dd++) {
        int col = dd * 8 + 2 * t;
        *(float2*)(g_C + r0 + col) =
            make_float2(f2tf32(o[dd][0] * inv0), f2tf32(o[dd][1] * inv0));
        *(float2*)(g_C + r1 + col) =
            make_float2(f2tf32(o[dd][2] * inv1), f2tf32(o[dd][3] * inv1));
    }
}

// ---------------------------------------------------------------------------
// kernel_launch
// Inputs: 0=X 1=position_ids 2=mask(unused,causal) 3=Wq 4=Wk 5=Wv 6=Wo 7=bo
// ---------------------------------------------------------------------------
extern "C" void kernel_launch(void* const* d_in, const int* in_sizes, int n_in,
                              void* d_out, int out_size)
{
    const float* X   = (const float*)d_in[0];
    const int*   pos = (const int*)d_in[1];
    const float* Wq  = (const float*)d_in[3];
    const float* Wk  = (const float*)d_in[4];
    const float* Wv  = (const float*)d_in[5];
    const float* Wo  = (const float*)d_in[6];
    const float* bo  = (const float*)d_in[7];
    float* out = (float*)d_out;

    cudaFuncSetAttribute(qkv_gemm_kernel,
                         cudaFuncAttributeMaxDynamicSharedMemorySize,
                         GEMM_SMEM_BYTES);
    cudaFuncSetAttribute(out_gemm_kernel,
                         cudaFuncAttributeMaxDynamicSharedMemorySize,
                         GEMM_SMEM_BYTES);
    cudaFuncSetAttribute(attn_kernel,
                         cudaFuncAttributeMaxDynamicSharedMemorySize,
                         ATT_SMEM_BYTES);

    float *dX, *dWq, *dWk, *dWv, *dWo;
    cudaGetSymbolAddress((void**)&dX,  g_X);
    cudaGetSymbolAddress((void**)&dWq, g_Wq);
    cudaGetSymbolAddress((void**)&dWk, g_Wk);
    cudaGetSymbolAddress((void**)&dWv, g_Wv);
    cudaGetSymbolAddress((void**)&dWo, g_Wo);

    const float rs = 0.08838834764831845f;   // 1/sqrt(128)
    int nx4 = MROWS * HDIM / 4;
    int nw4 = HDIM * HDIM / 4;
    cvt_tf32_kernel<<<nx4 / 256, 256>>>(X,  dX,  nx4, 1.f);
    cvt_tf32_kernel<<<nw4 / 256, 256>>>(Wq, dWq, nw4, rs);
    cvt_tf32_kernel<<<nw4 / 256, 256>>>(Wk, dWk, nw4, 1.f);
    cvt_tf32_kernel<<<nw4 / 256, 256>>>(Wv, dWv, nw4, 1.f);
    cvt_tf32_kernel<<<nw4 / 256, 256>>>(Wo, dWo, nw4, 1.f);

    dim3 g_qkv(HDIM / 256, MROWS / 128, 3);       // 8 x 32 x 3
    qkv_gemm_kernel<<<g_qkv, 256, GEMM_SMEM_BYTES>>>();

    int rope_threads = MROWS * NH * 64;
    rope_kernel<<<(rope_threads + 255) / 256, 256>>>(pos);

    dim3 g_att(S_LEN / 128, NH, NB);
    attn_kernel<<<g_att, 256, ATT_SMEM_BYTES>>>();

    dim3 g_out(HDIM / 256, MROWS / 128);          // 8 x 32
    out_gemm_kernel<<<g_out, 256, GEMM_SMEM_BYTES>>>(bo, out);
}

// round 8
// speedup vs baseline: 1.0796x; 1.0796x over previous
#include <cuda_runtime.h>
#include <math.h>
#include <stdint.h>

#define S_LEN 2048
#define HDIM  2048
#define NB    2
#define NH    16
#define DH    128
#define MROWS (NB * S_LEN)   // 4096

__device__ float g_Q[MROWS * HDIM];
__device__ float g_K[MROWS * HDIM];
__device__ float g_V[MROWS * HDIM];
__device__ float g_C[MROWS * HDIM];
__device__ float g_X[MROWS * HDIM];          // tf32-rounded X
__device__ float g_Wq[HDIM * HDIM];          // tf32-rounded, pre-scaled 1/sqrt(dh)
__device__ float g_Wk[HDIM * HDIM];
__device__ float g_Wv[HDIM * HDIM];
__device__ float g_Wo[HDIM * HDIM];

// ---------------------------------------------------------------------------
// TF32 helpers
// ---------------------------------------------------------------------------
__device__ __forceinline__ float f2tf32(float x)
{
    unsigned u;
    asm("cvt.rna.tf32.f32 %0, %1;" : "=r"(u) : "f"(x));
    return __uint_as_float(u);
}

__device__ __forceinline__ void mma_tf32(float* c, uint2 alo, uint2 ahi, uint2 b)
{
    asm("mma.sync.aligned.m16n8k8.row.col.f32.tf32.tf32.f32 "
        "{%0,%1,%2,%3}, {%4,%5,%6,%7}, {%8,%9}, {%0,%1,%2,%3};"
        : "+f"(c[0]), "+f"(c[1]), "+f"(c[2]), "+f"(c[3])
        : "r"(alo.x), "r"(ahi.x), "r"(alo.y), "r"(ahi.y),
          "r"(b.x),  "r"(b.y));
}

__device__ __forceinline__ void mma_tf32_r(float* c, float a0, float a1,
                                           float a2, float a3,
                                           float b0, float b1)
{
    asm("mma.sync.aligned.m16n8k8.row.col.f32.tf32.tf32.f32 "
        "{%0,%1,%2,%3}, {%4,%5,%6,%7}, {%8,%9}, {%0,%1,%2,%3};"
        : "+f"(c[0]), "+f"(c[1]), "+f"(c[2]), "+f"(c[3])
        : "r"(__float_as_uint(a0)), "r"(__float_as_uint(a1)),
          "r"(__float_as_uint(a2)), "r"(__float_as_uint(a3)),
          "r"(__float_as_uint(b0)), "r"(__float_as_uint(b1)));
}

__device__ __forceinline__ void cp_async16(uint32_t saddr, const float* g)
{
    asm volatile("cp.async.cg.shared.global [%0], [%1], 16;"
                 :: "r"(saddr), "l"(g));
}
#define CP_COMMIT() asm volatile("cp.async.commit_group;")
#define CP_WAIT(N)  asm volatile("cp.async.wait_group %0;" :: "n"(N))

// ---------------------------------------------------------------------------
// tf32 pre-rounding copy kernel (optionally scaled)
// ---------------------------------------------------------------------------
__global__ void cvt_tf32_kernel(const float* __restrict__ src,
                                float* __restrict__ dst,
                                int n4, float scale)
{
    int i = blockIdx.x * 256 + threadIdx.x;
    if (i >= n4) return;
    float4 v = ((const float4*)src)[i];
    v.x = f2tf32(v.x * scale);
    v.y = f2tf32(v.y * scale);
    v.z = f2tf32(v.z * scale);
    v.w = f2tf32(v.w * scale);
    ((float4*)dst)[i] = v;
}

// ---------------------------------------------------------------------------
// GEMM v5 = R5's v3 (128x128 CTA, 128 thr, 2 CTA/SM, 3-stage cp.async)
// + register double-buffered fragments across k8 steps.
// Smem: [row][8 float4-chunks], chunk j at j ^ (row&7). Operands pre-rounded.
// ---------------------------------------------------------------------------
#define GK 2048
#define TILE_F 4096              // 128 rows * 32 floats
#define GEMM_SMEM_BYTES (3 * TILE_F * 2 * 4)   // 96 KB

template <bool ROUND, bool HASBIAS>
__device__ __forceinline__ void gemm_v5_body(const float* __restrict__ A,
                                             const float* __restrict__ B,
                                             const float* __restrict__ bias,
                                             float* __restrict__ C)
{
    extern __shared__ float smem[];
    float* As = smem;
    float* Bs = smem + 3 * TILE_F;

    const int tid    = threadIdx.x;
    const int lane   = tid & 31;
    const int wid    = tid >> 5;
    const int warp_m = wid >> 1;
    const int warp_n = wid & 1;
    const int g      = lane >> 2;
    const int t      = lane & 3;
    const int bm     = blockIdx.y * 128;
    const int bn     = blockIdx.x * 128;

    const int ld_row0  = tid >> 3;
    const int ld_chunk = tid & 7;
    const float* gA = A + (size_t)(bm + ld_row0) * GK + ld_chunk * 4;
    const float* gB = B + (size_t)(bn + ld_row0) * GK + ld_chunk * 4;
    const int dst0 = ld_row0 * 32 + ((ld_chunk ^ (ld_row0 & 7)) << 2);

    uint32_t sA = (uint32_t)__cvta_generic_to_shared(As);
    uint32_t sB = (uint32_t)__cvta_generic_to_shared(Bs);

    auto issue = [&](int stage) {
        uint32_t da = sA + (stage * TILE_F + dst0) * 4;
        uint32_t db = sB + (stage * TILE_F + dst0) * 4;
#pragma unroll
        for (int it = 0; it < 8; it++)
            cp_async16(da + it * 512 * 4, gA + (size_t)it * 16 * GK);
#pragma unroll
        for (int it = 0; it < 8; it++)
            cp_async16(db + it * 512 * 4, gB + (size_t)it * 16 * GK);
        gA += 32;
        gB += 32;
        CP_COMMIT();
    };

    issue(0);
    issue(1);

    float acc[4][8][4];
#pragma unroll
    for (int mt = 0; mt < 4; mt++)
#pragma unroll
        for (int nt = 0; nt < 8; nt++)
#pragma unroll
            for (int i = 0; i < 4; i++) acc[mt][nt][i] = 0.f;

    int rbA[4], rbB[8];
#pragma unroll
    for (int mt = 0; mt < 4; mt++)
        rbA[mt] = (warp_m * 64 + mt * 16 + g) * 32;
#pragma unroll
    for (int nt = 0; nt < 8; nt++)
        rbB[nt] = (warp_n * 64 + nt * 8 + g) * 32;

    float a[2][4][4], b[2][8][2];

    const int nk = GK / 32;
    for (int kt = 0; kt < nk; kt++) {
        if (kt < nk - 1) { CP_WAIT(1); } else { CP_WAIT(0); }
        __syncthreads();
        if (kt + 2 < nk) issue((kt + 2) % 3);

        const float* as = As + (kt % 3) * TILE_F;
        const float* bs = Bs + (kt % 3) * TILE_F;

        // preload k8=0 fragments
        {
            const int o0 = ((0 ^ g) << 2) + t;
            const int o1 = ((1 ^ g) << 2) + t;
#pragma unroll
            for (int mt = 0; mt < 4; mt++) {
                a[0][mt][0] = as[rbA[mt] + o0];
                a[0][mt][1] = as[rbA[mt] + 256 + o0];
                a[0][mt][2] = as[rbA[mt] + o1];
                a[0][mt][3] = as[rbA[mt] + 256 + o1];
            }
#pragma unroll
            for (int nt = 0; nt < 8; nt++) {
                b[0][nt][0] = bs[rbB[nt] + o0];
                b[0][nt][1] = bs[rbB[nt] + o1];
            }
        }

#pragma unroll
        for (int k8 = 0; k8 < 4; k8++) {
            const int cur = k8 & 1;
            const int nxt = cur ^ 1;
            if (k8 < 3) {
                const int o0 = (((2 * (k8 + 1))     ^ g) << 2) + t;
                const int o1 = (((2 * (k8 + 1) + 1) ^ g) << 2) + t;
#pragma unroll
                for (int mt = 0; mt < 4; mt++) {
                    a[nxt][mt][0] = as[rbA[mt] + o0];
                    a[nxt][mt][1] = as[rbA[mt] + 256 + o0];
                    a[nxt][mt][2] = as[rbA[mt] + o1];
                    a[nxt][mt][3] = as[rbA[mt] + 256 + o1];
                }
#pragma unroll
                for (int nt = 0; nt < 8; nt++) {
                    b[nxt][nt][0] = bs[rbB[nt] + o0];
                    b[nxt][nt][1] = bs[rbB[nt] + o1];
                }
            }
#pragma unroll
            for (int mt = 0; mt < 4; mt++)
#pragma unroll
                for (int nt = 0; nt < 8; nt++)
                    mma_tf32_r(acc[mt][nt],
                               a[cur][mt][0], a[cur][mt][1],
                               a[cur][mt][2], a[cur][mt][3],
                               b[cur][nt][0], b[cur][nt][1]);
        }
    }

#pragma unroll
    for (int mt = 0; mt < 4; mt++) {
        int row = bm + warp_m * 64 + mt * 16 + g;
#pragma unroll
        for (int nt = 0; nt < 8; nt++) {
            int col = bn + warp_n * 64 + nt * 8 + 2 * t;
            float b0 = 0.f, b1 = 0.f;
            if (HASBIAS) { b0 = bias[col]; b1 = bias[col + 1]; }
            float v0 = acc[mt][nt][0] + b0, v1 = acc[mt][nt][1] + b1;
            float v2 = acc[mt][nt][2] + b0, v3 = acc[mt][nt][3] + b1;
            if (ROUND) {
                v0 = f2tf32(v0); v1 = f2tf32(v1);
                v2 = f2tf32(v2); v3 = f2tf32(v3);
            }
            *(float2*)(C + (size_t)row * HDIM + col)       = make_float2(v0, v1);
            *(float2*)(C + (size_t)(row + 8) * HDIM + col) = make_float2(v2, v3);
        }
    }
}

__global__ void __launch_bounds__(128, 2) qkv_gemm_kernel()
{
    const float* B = (blockIdx.z == 0) ? g_Wq : (blockIdx.z == 1) ? g_Wk : g_Wv;
    float* C       = (blockIdx.z == 0) ? g_Q  : (blockIdx.z == 1) ? g_K  : g_V;
    gemm_v5_body<true, false>(g_X, B, nullptr, C);
}

__global__ void __launch_bounds__(128, 2) out_gemm_kernel(
    const float* __restrict__ bo, float* __restrict__ out)
{
    gemm_v5_body<false, true>(g_C, g_Wo, bo, out);
}

// ---------------------------------------------------------------------------
// RoPE in-place on g_Q, g_K (writes tf32-rounded)
// ---------------------------------------------------------------------------
__global__ void rope_kernel(const int* __restrict__ pos_ids)
{
    int idx = blockIdx.x * 256 + threadIdx.x;
    if (idx >= MROWS * NH * 64) return;
    int d = idx & 63;
    int h = (idx >> 6) & 15;
    int m = idx >> 10;
    int s = m & (S_LEN - 1);

    float p = (float)pos_ids[s];
    float theta = expf(-0.14391156531392624f * (float)d);
    float ang = p * theta;
    float sn, cs;
    sincosf(ang, &sn, &cs);

    size_t base = (size_t)m * HDIM + h * DH + d;
    float q1 = g_Q[base], q2 = g_Q[base + 64];
    g_Q[base]      = f2tf32(q1 * cs - q2 * sn);
    g_Q[base + 64] = f2tf32(q1 * sn + q2 * cs);
    float k1 = g_K[base], k2 = g_K[base + 64];
    g_K[base]      = f2tf32(k1 * cs - k2 * sn);
    g_K[base + 64] = f2tf32(k1 * sn + k2 * cs);
}

// ---------------------------------------------------------------------------
// TF32 MMA flash attention (unchanged from R5). Sources pre-rounded.
// ---------------------------------------------------------------------------
#define CQ 1034
#define CK 522
#define VSTRIDE 132
#define ATT_SMEM_FLOATS (16 * CQ + 16 * CK + 64 * VSTRIDE)
#define ATT_SMEM_BYTES  (ATT_SMEM_FLOATS * 4)

__global__ void __launch_bounds__(256) attn_kernel()
{
    extern __shared__ float sm[];
    float* Qs = sm;
    float* Ks = Qs + 16 * CQ;
    float* Vs = Ks + 16 * CK;

    const int tid  = threadIdx.x;
    const int lane = tid & 31;
    const int w    = tid >> 5;
    const int g    = lane >> 2;
    const int t    = lane & 3;
    const int qt   = (gridDim.x - 1) - blockIdx.x;
    const int h    = blockIdx.y;
    const int n    = blockIdx.z;
    const int q0   = qt * 128;

    const size_t rowbase = (size_t)n * S_LEN;
    const size_t hoff    = (size_t)h * DH;

#pragma unroll
    for (int it = 0; it < 16; it++) {
        int id = tid + it * 256;
        int r  = id >> 5;
        int f4 = id & 31;
        int so = (f4 >> 1) * CQ + r * 8 + (f4 & 1);
        float4 v = *(const float4*)(g_Q + (rowbase + q0 + r) * HDIM + hoff + f4 * 4);
        Qs[so + 0] = v.x;
        Qs[so + 2] = v.y;
        Qs[so + 4] = v.z;
        Qs[so + 6] = v.w;
    }

    float o[16][4];
#pragma unroll
    for (int dd = 0; dd < 16; dd++)
#pragma unroll
        for (int i = 0; i < 4; i++) o[dd][i] = 0.f;
    float m0 = -1e30f, m1 = -1e30f, l0 = 0.f, l1 = 0.f;

    const int row0 = q0 + w * 16 + g;
    const int nkt  = 2 * (qt + 1);

    for (int kt = 0; kt < nkt; kt++) {
        __syncthreads();
        const int k0 = kt * 64;
#pragma unroll
        for (int it = 0; it < 8; it++) {
            int id = tid + it * 256;
            int r  = id >> 5;
            int f4 = id & 31;
            size_t gg = (rowbase + k0 + r) * HDIM + hoff + f4 * 4;
            float4 vk = *(const float4*)(g_K + gg);
            int so = (f4 >> 1) * CK + r * 8 + (f4 & 1);
            Ks[so + 0] = vk.x;
            Ks[so + 2] = vk.y;
            Ks[so + 4] = vk.z;
            Ks[so + 6] = vk.w;
            *(float4*)&Vs[r * VSTRIDE + f4 * 4] = *(const float4*)(g_V + gg);
        }
        __syncthreads();

        float s[8][4];
#pragma unroll
        for (int nn = 0; nn < 8; nn++)
#pragma unroll
            for (int i = 0; i < 4; i++) s[nn][i] = 0.f;

#pragma unroll
        for (int c = 0; c < 16; c++) {
            const float* qp = &Qs[c * CQ + (w * 16 + g) * 8 + 2 * t];
            uint2 alo = *(const uint2*)qp;
            uint2 ahi = *(const uint2*)(qp + 64);
#pragma unroll
            for (int nn = 0; nn < 8; nn++) {
                uint2 b = *(const uint2*)&Ks[c * CK + (nn * 8 + g) * 8 + 2 * t];
                mma_tf32(s[nn], alo, ahi, b);
            }
        }

        if (k0 + 63 > row0) {
#pragma unroll
            for (int nn = 0; nn < 8; nn++) {
                int col = k0 + nn * 8 + 2 * t;
                if (col > row0)     s[nn][0] = -1e30f;
                if (col + 1 > row0) s[nn][1] = -1e30f;
                if (col > row0 + 8)     s[nn][2] = -1e30f;
                if (col + 1 > row0 + 8) s[nn][3] = -1e30f;
            }
        }

        float mx0 = -1e30f, mx1 = -1e30f;
#pragma unroll
        for (int nn = 0; nn < 8; nn++) {
            mx0 = fmaxf(mx0, fmaxf(s[nn][0], s[nn][1]));
            mx1 = fmaxf(mx1, fmaxf(s[nn][2], s[nn][3]));
        }
        mx0 = fmaxf(mx0, __shfl_xor_sync(0xffffffffu, mx0, 1));
        mx0 = fmaxf(mx0, __shfl_xor_sync(0xffffffffu, mx0, 2));
        mx1 = fmaxf(mx1, __shfl_xor_sync(0xffffffffu, mx1, 1));
        mx1 = fmaxf(mx1, __shfl_xor_sync(0xffffffffu, mx1, 2));

        float newm0 = fmaxf(m0, mx0);
        float newm1 = fmaxf(m1, mx1);
        float alpha0 = __expf(m0 - newm0);
        float alpha1 = __expf(m1 - newm1);
        m0 = newm0; m1 = newm1;

        float sum0 = 0.f, sum1 = 0.f;
#pragma unroll
        for (int nn = 0; nn < 8; nn++) {
            float p0 = f2tf32(__expf(s[nn][0] - newm0));
            float p1 = f2tf32(__expf(s[nn][1] - newm0));
            float p2 = f2tf32(__expf(s[nn][2] - newm1));
            float p3 = f2tf32(__expf(s[nn][3] - newm1));
            s[nn][0] = p0; s[nn][1] = p1; s[nn][2] = p2; s[nn][3] = p3;
            sum0 += p0 + p1;
            sum1 += p2 + p3;
        }
        sum0 += __shfl_xor_sync(0xffffffffu, sum0, 1);
        sum0 += __shfl_xor_sync(0xffffffffu, sum0, 2);
        sum1 += __shfl_xor_sync(0xffffffffu, sum1, 1);
        sum1 += __shfl_xor_sync(0xffffffffu, sum1, 2);
        l0 = l0 * alpha0 + sum0;
        l1 = l1 * alpha1 + sum1;

#pragma unroll
        for (int dd = 0; dd < 16; dd++) {
            o[dd][0] *= alpha0; o[dd][1] *= alpha0;
            o[dd][2] *= alpha1; o[dd][3] *= alpha1;
        }

#pragma unroll
        for (int c8 = 0; c8 < 8; c8++) {
            const float* vp = &Vs[(c8 * 8 + 2 * t) * VSTRIDE + g];
#pragma unroll
            for (int dd = 0; dd < 16; dd++) {
                float b0 = vp[dd * 8];
                float b1 = vp[dd * 8 + VSTRIDE];
                mma_tf32_r(o[dd], s[c8][0], s[c8][2], s[c8][1], s[c8][3], b0, b1);
            }
        }
    }

    float inv0 = 1.f / l0;
    float inv1 = 1.f / l1;
    size_t r0 = (rowbase + row0) * HDIM + hoff;
    size_t r1 = r0 + 8 * HDIM;
#pragma unroll
    for (int dd = 0; dd < 16; dd++) {
        int col = dd * 8 + 2 * t;
        *(float2*)(g_C + r0 + col) =
            make_float2(f2tf32(o[dd][0] * inv0), f2tf32(o[dd][1] * inv0));
        *(float2*)(g_C + r1 + col) =
            make_float2(f2tf32(o[dd][2] * inv1), f2tf32(o[dd][3] * inv1));
    }
}

// ---------------------------------------------------------------------------
// kernel_launch
// Inputs: 0=X 1=position_ids 2=mask(unused,causal) 3=Wq 4=Wk 5=Wv 6=Wo 7=bo
// ---------------------------------------------------------------------------
extern "C" void kernel_launch(void* const* d_in, const int* in_sizes, int n_in,
                              void* d_out, int out_size)
{
    const float* X   = (const float*)d_in[0];
    const int*   pos = (const int*)d_in[1];
    const float* Wq  = (const float*)d_in[3];
    const float* Wk  = (const float*)d_in[4];
    const float* Wv  = (const float*)d_in[5];
    const float* Wo  = (const float*)d_in[6];
    const float* bo  = (const float*)d_in[7];
    float* out = (float*)d_out;

    cudaFuncSetAttribute(qkv_gemm_kernel,
                         cudaFuncAttributeMaxDynamicSharedMemorySize,
                         GEMM_SMEM_BYTES);
    cudaFuncSetAttribute(out_gemm_kernel,
                         cudaFuncAttributeMaxDynamicSharedMemorySize,
                         GEMM_SMEM_BYTES);
    cudaFuncSetAttribute(attn_kernel,
                         cudaFuncAttributeMaxDynamicSharedMemorySize,
                         ATT_SMEM_BYTES);

    float *dX, *dWq, *dWk, *dWv, *dWo;
    cudaGetSymbolAddress((void**)&dX,  g_X);
    cudaGetSymbolAddress((void**)&dWq, g_Wq);
    cudaGetSymbolAddress((void**)&dWk, g_Wk);
    cudaGetSymbolAddress((void**)&dWv, g_Wv);
    cudaGetSymbolAddress((void**)&dWo, g_Wo);

    const float rs = 0.08838834764831845f;   // 1/sqrt(128)
    int nx4 = MROWS * HDIM / 4;
    int nw4 = HDIM * HDIM / 4;
    cvt_tf32_kernel<<<nx4 / 256, 256>>>(X,  dX,  nx4, 1.f);
    cvt_tf32_kernel<<<nw4 / 256, 256>>>(Wq, dWq, nw4, rs);
    cvt_tf32_kernel<<<nw4 / 256, 256>>>(Wk, dWk, nw4, 1.f);
    cvt_tf32_kernel<<<nw4 / 256, 256>>>(Wv, dWv, nw4, 1.f);
    cvt_tf32_kernel<<<nw4 / 256, 256>>>(Wo, dWo, nw4, 1.f);

    dim3 g_qkv(HDIM / 128, MROWS / 128, 3);
    qkv_gemm_kernel<<<g_qkv, 128, GEMM_SMEM_BYTES>>>();

    int rope_threads = MROWS * NH * 64;
    rope_kernel<<<(rope_threads + 255) / 256, 256>>>(pos);

    dim3 g_att(S_LEN / 128, NH, NB);
    attn_kernel<<<g_att, 256, ATT_SMEM_BYTES>>>();

    dim3 g_out(HDIM / 128, MROWS / 128);
    out_gemm_kernel<<<g_out, 128, GEMM_SMEM_BYTES>>>(bo, out);
}

// round 9
// speedup vs baseline: 1.2999x; 1.2040x over previous
#include <cuda_runtime.h>
#include <cuda_fp16.h>
#include <math.h>
#include <stdint.h>

#define S_LEN 2048
#define HDIM  2048
#define NB    2
#define NH    16
#define DH    128
#define MROWS (NB * S_LEN)   // 4096

__device__ __half g_Q[MROWS * HDIM];
__device__ __half g_K[MROWS * HDIM];
__device__ __half g_V[MROWS * HDIM];
__device__ __half g_C[MROWS * HDIM];
__device__ __half g_X[MROWS * HDIM];         // fp16-rounded X
__device__ __half g_Wq[HDIM * HDIM];         // fp16-rounded, pre-scaled 1/sqrt(dh)
__device__ __half g_Wk[HDIM * HDIM];
__device__ __half g_Wv[HDIM * HDIM];
__device__ __half g_Wo[HDIM * HDIM];

// ---------------------------------------------------------------------------
// fp16 MMA: D(f32) += A(m16k16 f16,row) * B(k16n8 f16,col)
// a0=(g,2t:2t+1) a1=(g+8,2t:2t+1) a2=(g,2t+8:2t+9) a3=(g+8,2t+8:2t+9)
// b0=(2t:2t+1,g) b1=(2t+8:2t+9,g); c0,c1=(g,2t,2t+1) c2,c3=(g+8,...)
// ---------------------------------------------------------------------------
__device__ __forceinline__ void mma_f16(float* c, uint32_t a0, uint32_t a1,
                                        uint32_t a2, uint32_t a3,
                                        uint32_t b0, uint32_t b1)
{
    asm("mma.sync.aligned.m16n8k16.row.col.f32.f16.f16.f32 "
        "{%0,%1,%2,%3}, {%4,%5,%6,%7}, {%8,%9}, {%0,%1,%2,%3};"
        : "+f"(c[0]), "+f"(c[1]), "+f"(c[2]), "+f"(c[3])
        : "r"(a0), "r"(a1), "r"(a2), "r"(a3), "r"(b0), "r"(b1));
}

__device__ __forceinline__ uint32_t pack_h2(float lo, float hi)
{
    __half2 h = __floats2half2_rn(lo, hi);
    return *(uint32_t*)&h;
}

__device__ __forceinline__ void cp_async16(uint32_t saddr, const void* g)
{
    asm volatile("cp.async.cg.shared.global [%0], [%1], 16;"
                 :: "r"(saddr), "l"(g));
}
#define CP_COMMIT() asm volatile("cp.async.commit_group;")
#define CP_WAIT(N)  asm volatile("cp.async.wait_group %0;" :: "n"(N))

// ---------------------------------------------------------------------------
// fp32 -> fp16 pre-rounding copy (optionally scaled); 8 elements/thread
// ---------------------------------------------------------------------------
__global__ void cvt_f16_kernel(const float* __restrict__ src,
                               __half* __restrict__ dst,
                               int n8, float scale)
{
    int i = blockIdx.x * 256 + threadIdx.x;
    if (i >= n8) return;
    float4 v0 = ((const float4*)src)[2 * i];
    float4 v1 = ((const float4*)src)[2 * i + 1];
    uint4 o;
    o.x = pack_h2(v0.x * scale, v0.y * scale);
    o.y = pack_h2(v0.z * scale, v0.w * scale);
    o.z = pack_h2(v1.x * scale, v1.y * scale);
    o.w = pack_h2(v1.z * scale, v1.w * scale);
    ((uint4*)dst)[i] = o;
}

// ---------------------------------------------------------------------------
// fp16 GEMM: C[M,2048] = A[M,2048] @ B[2048,2048]^T (+bias)
// CTA 128x128, 128 thr = 4 warps (2m x 2n), warp tile 64x64, BK=32 halves.
// 3-stage cp.async. Smem rows padded 64B->80B (stride 40 halves):
// row bank offset = 20*row mod 32 = {0,20,8,28,16,4,24,12} -> frag LDS
// conflict-free, no XOR swizzle needed.
// ---------------------------------------------------------------------------
#define GK 2048
#define STAGE_B 10240                     // 128 rows * 80 bytes
#define STAGE_H 5120                      // halves
#define GEMM_SMEM_BYTES (3 * 2 * STAGE_B) // 61440

template <bool TOHALF, bool HASBIAS>
__device__ __forceinline__ void gemm_f16_body(const __half* __restrict__ A,
                                              const __half* __restrict__ B,
                                              const float* __restrict__ bias,
                                              void* __restrict__ Cout)
{
    extern __shared__ __align__(16) char smem[];
    uint32_t sbase = (uint32_t)__cvta_generic_to_shared(smem);

    const int tid    = threadIdx.x;
    const int lane   = tid & 31;
    const int wid    = tid >> 5;
    const int warp_m = wid >> 1;
    const int warp_n = wid & 1;
    const int g      = lane >> 2;
    const int t      = lane & 3;
    const int bm     = blockIdx.y * 128;
    const int bn     = blockIdx.x * 128;

    // loader: row tr+32*it (4 its), 16B chunk tc (4 per row)
    const int tr = tid >> 2;              // 0..31
    const int tc = tid & 3;
    const __half* gA = A + (size_t)(bm + tr) * GK + tc * 8;
    const __half* gB = B + (size_t)(bn + tr) * GK + tc * 8;
    const uint32_t dst0 = tr * 80 + tc * 16;

    auto issue = [&](int stage) {
        uint32_t da = sbase + stage * STAGE_B + dst0;
        uint32_t db = da + 3 * STAGE_B;
#pragma unroll
        for (int it = 0; it < 4; it++)
            cp_async16(da + it * 32 * 80, gA + (size_t)it * 32 * GK);
#pragma unroll
        for (int it = 0; it < 4; it++)
            cp_async16(db + it * 32 * 80, gB + (size_t)it * 32 * GK);
        gA += 32;
        gB += 32;
        CP_COMMIT();
    };

    issue(0);
    issue(1);

    float acc[4][8][4];
#pragma unroll
    for (int mt = 0; mt < 4; mt++)
#pragma unroll
        for (int nt = 0; nt < 8; nt++)
#pragma unroll
            for (int i = 0; i < 4; i++) acc[mt][nt][i] = 0.f;

    int rbA[4], rbB[8];   // half-index row bases
#pragma unroll
    for (int mt = 0; mt < 4; mt++)
        rbA[mt] = (warp_m * 64 + mt * 16 + g) * 40;
#pragma unroll
    for (int nt = 0; nt < 8; nt++)
        rbB[nt] = (warp_n * 64 + nt * 8 + g) * 40;

    const int nk = GK / 32;   // 64
    for (int kt = 0; kt < nk; kt++) {
        if (kt < nk - 1) { CP_WAIT(1); } else { CP_WAIT(0); }
        __syncthreads();
        if (kt + 2 < nk) issue((kt + 2) % 3);

        const __half* as = (const __half*)(smem + (kt % 3) * STAGE_B);
        const __half* bs = (const __half*)(smem + 3 * STAGE_B + (kt % 3) * STAGE_B);

#pragma unroll
        for (int kg = 0; kg < 2; kg++) {
            const int ko = kg * 16 + 2 * t;
            uint32_t a[4][4];
#pragma unroll
            for (int mt = 0; mt < 4; mt++) {
                a[mt][0] = *(const uint32_t*)&as[rbA[mt] + ko];
                a[mt][1] = *(const uint32_t*)&as[rbA[mt] + 8 * 40 + ko];
                a[mt][2] = *(const uint32_t*)&as[rbA[mt] + ko + 8];
                a[mt][3] = *(const uint32_t*)&as[rbA[mt] + 8 * 40 + ko + 8];
            }
            uint32_t b[8][2];
#pragma unroll
            for (int nt = 0; nt < 8; nt++) {
                b[nt][0] = *(const uint32_t*)&bs[rbB[nt] + ko];
                b[nt][1] = *(const uint32_t*)&bs[rbB[nt] + ko + 8];
            }
#pragma unroll
            for (int mt = 0; mt < 4; mt++)
#pragma unroll
                for (int nt = 0; nt < 8; nt++)
                    mma_f16(acc[mt][nt], a[mt][0], a[mt][1], a[mt][2], a[mt][3],
                            b[nt][0], b[nt][1]);
        }
    }

#pragma unroll
    for (int mt = 0; mt < 4; mt++) {
        int row = bm + warp_m * 64 + mt * 16 + g;
#pragma unroll
        for (int nt = 0; nt < 8; nt++) {
            int col = bn + warp_n * 64 + nt * 8 + 2 * t;
            if (TOHALF) {
                __half* C = (__half*)Cout;
                *(__half2*)(C + (size_t)row * HDIM + col) =
                    __floats2half2_rn(acc[mt][nt][0], acc[mt][nt][1]);
                *(__half2*)(C + (size_t)(row + 8) * HDIM + col) =
                    __floats2half2_rn(acc[mt][nt][2], acc[mt][nt][3]);
            } else {
                float* C = (float*)Cout;
                float b0 = 0.f, b1 = 0.f;
                if (HASBIAS) { b0 = bias[col]; b1 = bias[col + 1]; }
                *(float2*)(C + (size_t)row * HDIM + col) =
                    make_float2(acc[mt][nt][0] + b0, acc[mt][nt][1] + b1);
                *(float2*)(C + (size_t)(row + 8) * HDIM + col) =
                    make_float2(acc[mt][nt][2] + b0, acc[mt][nt][3] + b1);
            }
        }
    }
}

__global__ void __launch_bounds__(128, 2) qkv_gemm_kernel()
{
    const __half* B = (blockIdx.z == 0) ? g_Wq : (blockIdx.z == 1) ? g_Wk : g_Wv;
    __half* C       = (blockIdx.z == 0) ? g_Q  : (blockIdx.z == 1) ? g_K  : g_V;
    gemm_f16_body<true, false>(g_X, B, nullptr, C);
}

__global__ void __launch_bounds__(128, 2) out_gemm_kernel(
    const float* __restrict__ bo, float* __restrict__ out)
{
    gemm_f16_body<false, true>(g_C, g_Wo, bo, out);
}

// ---------------------------------------------------------------------------
// RoPE in-place on g_Q, g_K (fp16 storage, fp32 math)
// ---------------------------------------------------------------------------
__global__ void rope_kernel(const int* __restrict__ pos_ids)
{
    int idx = blockIdx.x * 256 + threadIdx.x;
    if (idx >= MROWS * NH * 64) return;
    int d = idx & 63;
    int h = (idx >> 6) & 15;
    int m = idx >> 10;
    int s = m & (S_LEN - 1);

    float p = (float)pos_ids[s];
    float theta = expf(-0.14391156531392624f * (float)d);
    float ang = p * theta;
    float sn, cs;
    sincosf(ang, &sn, &cs);

    size_t base = (size_t)m * HDIM + h * DH + d;
    float q1 = __half2float(g_Q[base]), q2 = __half2float(g_Q[base + 64]);
    g_Q[base]      = __float2half_rn(q1 * cs - q2 * sn);
    g_Q[base + 64] = __float2half_rn(q1 * sn + q2 * cs);
    float k1 = __half2float(g_K[base]), k2 = __half2float(g_K[base + 64]);
    g_K[base]      = __float2half_rn(k1 * cs - k2 * sn);
    g_K[base + 64] = __float2half_rn(k1 * sn + k2 * cs);
}

// ---------------------------------------------------------------------------
// fp16 MMA flash attention. CTA: 128 q x 64 kv, dh=128, 8 warps (16 q each).
// Qs [128][136] halves, Ks [64][136], Vt transposed [128 d][72 kv] halves —
// padded strides (272B/144B => 4-bank row offsets) keep frag LDS conflict-free.
// P c-frags repack to fp16 A-frags; V^T gives contiguous kv pairs for B.
// ---------------------------------------------------------------------------
#define QSTR 136
#define KSTR 136
#define VSTR 72
#define ATT_SMEM_BYTES ((128 * QSTR + 64 * KSTR + 128 * VSTR) * 2)

__global__ void __launch_bounds__(256) attn_kernel()
{
    extern __shared__ __align__(16) __half smh[];
    __half* Qs = smh;
    __half* Ks = Qs + 128 * QSTR;
    __half* Vt = Ks + 64 * KSTR;

    const int tid  = threadIdx.x;
    const int lane = tid & 31;
    const int w    = tid >> 5;
    const int g    = lane >> 2;
    const int t    = lane & 3;
    const int qt   = (gridDim.x - 1) - blockIdx.x;   // heavy tiles first
    const int h    = blockIdx.y;
    const int n    = blockIdx.z;
    const int q0   = qt * 128;

    const size_t rowbase = (size_t)n * S_LEN;
    const size_t hoff    = (size_t)h * DH;

    // Load Q tile: 128 rows x 16 uint4
#pragma unroll
    for (int it = 0; it < 8; it++) {
        int id = tid + it * 256;
        int r  = id >> 4;
        int c  = id & 15;
        *(uint4*)&Qs[r * QSTR + c * 8] =
            *(const uint4*)(g_Q + (rowbase + q0 + r) * HDIM + hoff + c * 8);
    }

    float o[16][4];
#pragma unroll
    for (int dd = 0; dd < 16; dd++)
#pragma unroll
        for (int i = 0; i < 4; i++) o[dd][i] = 0.f;
    float m0 = -1e30f, m1 = -1e30f, l0 = 0.f, l1 = 0.f;

    const int row0 = q0 + w * 16 + g;
    const int nkt  = 2 * (qt + 1);

    for (int kt = 0; kt < nkt; kt++) {
        __syncthreads();
        const int k0 = kt * 64;
        // K: 64 rows x 16 uint4; V: transpose to Vt[d][kv]
#pragma unroll
        for (int it = 0; it < 4; it++) {
            int id = tid + it * 256;
            int r  = id >> 4;
            int c  = id & 15;
            size_t gg = (rowbase + k0 + r) * HDIM + hoff + c * 8;
            *(uint4*)&Ks[r * KSTR + c * 8] = *(const uint4*)(g_K + gg);
            uint4 vv = *(const uint4*)(g_V + gg);
            const __half* vh = (const __half*)&vv;
#pragma unroll
            for (int j = 0; j < 8; j++)
                Vt[(c * 8 + j) * VSTR + r] = vh[j];
        }
        __syncthreads();

        // ---- S = Q K^T : 8 n-blocks x 8 k16-groups ----
        float s[8][4];
#pragma unroll
        for (int nn = 0; nn < 8; nn++)
#pragma unroll
            for (int i = 0; i < 4; i++) s[nn][i] = 0.f;

        const int qrow = (w * 16 + g) * QSTR;
#pragma unroll
        for (int kg = 0; kg < 8; kg++) {
            const int ko = kg * 16 + 2 * t;
            uint32_t a0 = *(const uint32_t*)&Qs[qrow + ko];
            uint32_t a1 = *(const uint32_t*)&Qs[qrow + 8 * QSTR + ko];
            uint32_t a2 = *(const uint32_t*)&Qs[qrow + ko + 8];
            uint32_t a3 = *(const uint32_t*)&Qs[qrow + 8 * QSTR + ko + 8];
#pragma unroll
            for (int nn = 0; nn < 8; nn++) {
                const int krow = (nn * 8 + g) * KSTR;
                uint32_t b0 = *(const uint32_t*)&Ks[krow + ko];
                uint32_t b1 = *(const uint32_t*)&Ks[krow + ko + 8];
                mma_f16(s[nn], a0, a1, a2, a3, b0, b1);
            }
        }

        // ---- causal mask ----
        if (k0 + 63 > row0) {
#pragma unroll
            for (int nn = 0; nn < 8; nn++) {
                int col = k0 + nn * 8 + 2 * t;
                if (col > row0)     s[nn][0] = -1e30f;
                if (col + 1 > row0) s[nn][1] = -1e30f;
                if (col > row0 + 8)     s[nn][2] = -1e30f;
                if (col + 1 > row0 + 8) s[nn][3] = -1e30f;
            }
        }

        // ---- online softmax ----
        float mx0 = -1e30f, mx1 = -1e30f;
#pragma unroll
        for (int nn = 0; nn < 8; nn++) {
            mx0 = fmaxf(mx0, fmaxf(s[nn][0], s[nn][1]));
            mx1 = fmaxf(mx1, fmaxf(s[nn][2], s[nn][3]));
        }
        mx0 = fmaxf(mx0, __shfl_xor_sync(0xffffffffu, mx0, 1));
        mx0 = fmaxf(mx0, __shfl_xor_sync(0xffffffffu, mx0, 2));
        mx1 = fmaxf(mx1, __shfl_xor_sync(0xffffffffu, mx1, 1));
        mx1 = fmaxf(mx1, __shfl_xor_sync(0xffffffffu, mx1, 2));

        float newm0 = fmaxf(m0, mx0);
        float newm1 = fmaxf(m1, mx1);
        float alpha0 = __expf(m0 - newm0);
        float alpha1 = __expf(m1 - newm1);
        m0 = newm0; m1 = newm1;

        float sum0 = 0.f, sum1 = 0.f;
#pragma unroll
        for (int nn = 0; nn < 8; nn++) {
            s[nn][0] = __expf(s[nn][0] - newm0);
            s[nn][1] = __expf(s[nn][1] - newm0);
            s[nn][2] = __expf(s[nn][2] - newm1);
            s[nn][3] = __expf(s[nn][3] - newm1);
            sum0 += s[nn][0] + s[nn][1];
            sum1 += s[nn][2] + s[nn][3];
        }
        sum0 += __shfl_xor_sync(0xffffffffu, sum0, 1);
        sum0 += __shfl_xor_sync(0xffffffffu, sum0, 2);
        sum1 += __shfl_xor_sync(0xffffffffu, sum1, 1);
        sum1 += __shfl_xor_sync(0xffffffffu, sum1, 2);
        l0 = l0 * alpha0 + sum0;
        l1 = l1 * alpha1 + sum1;

#pragma unroll
        for (int dd = 0; dd < 16; dd++) {
            o[dd][0] *= alpha0; o[dd][1] *= alpha0;
            o[dd][2] *= alpha1; o[dd][3] *= alpha1;
        }

        // ---- O += P V : P packed as fp16 A-frags, B from Vt ----
#pragma unroll
        for (int kg = 0; kg < 4; kg++) {
            uint32_t a0 = pack_h2(s[2 * kg][0],     s[2 * kg][1]);
            uint32_t a1 = pack_h2(s[2 * kg][2],     s[2 * kg][3]);
            uint32_t a2 = pack_h2(s[2 * kg + 1][0], s[2 * kg + 1][1]);
            uint32_t a3 = pack_h2(s[2 * kg + 1][2], s[2 * kg + 1][3]);
            const int ko = kg * 16 + 2 * t;
#pragma unroll
            for (int dd = 0; dd < 16; dd++) {
                const int vrow = (dd * 8 + g) * VSTR;
                uint32_t b0 = *(const uint32_t*)&Vt[vrow + ko];
                uint32_t b1 = *(const uint32_t*)&Vt[vrow + ko + 8];
                mma_f16(o[dd], a0, a1, a2, a3, b0, b1);
            }
        }
    }

    // ---- epilogue: normalize, write fp16 context ----
    float inv0 = 1.f / l0;
    float inv1 = 1.f / l1;
    size_t r0 = (rowbase + row0) * HDIM + hoff;
    size_t r1 = r0 + 8 * HDIM;
#pragma unroll
    for (int dd = 0; dd < 16; dd++) {
        int col = dd * 8 + 2 * t;
        *(__half2*)(g_C + r0 + col) =
            __floats2half2_rn(o[dd][0] * inv0, o[dd][1] * inv0);
        *(__half2*)(g_C + r1 + col) =
            __floats2half2_rn(o[dd][2] * inv1, o[dd][3] * inv1);
    }
}

// ---------------------------------------------------------------------------
// kernel_launch
// Inputs: 0=X 1=position_ids 2=mask(unused,causal) 3=Wq 4=Wk 5=Wv 6=Wo 7=bo
// ---------------------------------------------------------------------------
extern "C" void kernel_launch(void* const* d_in, const int* in_sizes, int n_in,
                              void* d_out, int out_size)
{
    const float* X   = (const float*)d_in[0];
    const int*   pos = (const int*)d_in[1];
    const float* Wq  = (const float*)d_in[3];
    const float* Wk  = (const float*)d_in[4];
    const float* Wv  = (const float*)d_in[5];
    const float* Wo  = (const float*)d_in[6];
    const float* bo  = (const float*)d_in[7];
    float* out = (float*)d_out;

    cudaFuncSetAttribute(qkv_gemm_kernel,
                         cudaFuncAttributeMaxDynamicSharedMemorySize,
                         GEMM_SMEM_BYTES);
    cudaFuncSetAttribute(out_gemm_kernel,
                         cudaFuncAttributeMaxDynamicSharedMemorySize,
                         GEMM_SMEM_BYTES);
    cudaFuncSetAttribute(attn_kernel,
                         cudaFuncAttributeMaxDynamicSharedMemorySize,
                         ATT_SMEM_BYTES);

    __half *dX, *dWq, *dWk, *dWv, *dWo;
    cudaGetSymbolAddress((void**)&dX,  g_X);
    cudaGetSymbolAddress((void**)&dWq, g_Wq);
    cudaGetSymbolAddress((void**)&dWk, g_Wk);
    cudaGetSymbolAddress((void**)&dWv, g_Wv);
    cudaGetSymbolAddress((void**)&dWo, g_Wo);

    const float rs = 0.08838834764831845f;   // 1/sqrt(128)
    int nx8 = MROWS * HDIM / 8;
    int nw8 = HDIM * HDIM / 8;
    cvt_f16_kernel<<<nx8 / 256, 256>>>(X,  dX,  nx8, 1.f);
    cvt_f16_kernel<<<nw8 / 256, 256>>>(Wq, dWq, nw8, rs);
    cvt_f16_kernel<<<nw8 / 256, 256>>>(Wk, dWk, nw8, 1.f);
    cvt_f16_kernel<<<nw8 / 256, 256>>>(Wv, dWv, nw8, 1.f);
    cvt_f16_kernel<<<nw8 / 256, 256>>>(Wo, dWo, nw8, 1.f);

    dim3 g_qkv(HDIM / 128, MROWS / 128, 3);
    qkv_gemm_kernel<<<g_qkv, 128, GEMM_SMEM_BYTES>>>();

    int rope_threads = MROWS * NH * 64;
    rope_kernel<<<(rope_threads + 255) / 256, 256>>>(pos);

    dim3 g_att(S_LEN / 128, NH, NB);
    attn_kernel<<<g_att, 256, ATT_SMEM_BYTES>>>();

    dim3 g_out(HDIM / 128, MROWS / 128);
    out_gemm_kernel<<<g_out, 128, GEMM_SMEM_BYTES>>>(bo, out);
}

// round 10
// speedup vs baseline: 1.4605x; 1.1236x over previous
#include <cuda_runtime.h>
#include <cuda_fp16.h>
#include <math.h>
#include <stdint.h>

#define S_LEN 2048
#define HDIM  2048
#define NB    2
#define NH    16
#define DH    128
#define MROWS (NB * S_LEN)   // 4096

__device__ __half g_Q[MROWS * HDIM];
__device__ __half g_K[MROWS * HDIM];
__device__ __half g_V[MROWS * HDIM];
__device__ __half g_C[MROWS * HDIM];
__device__ __half g_X[MROWS * HDIM];
__device__ __half g_Wq[HDIM * HDIM];         // pre-scaled 1/sqrt(dh)
__device__ __half g_Wk[HDIM * HDIM];
__device__ __half g_Wv[HDIM * HDIM];
__device__ __half g_Wo[HDIM * HDIM];

// ---------------------------------------------------------------------------
// fp16 MMA m16n8k16 + ldmatrix helpers
// ---------------------------------------------------------------------------
__device__ __forceinline__ void mma_f16(float* c, uint32_t a0, uint32_t a1,
                                        uint32_t a2, uint32_t a3,
                                        uint32_t b0, uint32_t b1)
{
    asm("mma.sync.aligned.m16n8k16.row.col.f32.f16.f16.f32 "
        "{%0,%1,%2,%3}, {%4,%5,%6,%7}, {%8,%9}, {%0,%1,%2,%3};"
        : "+f"(c[0]), "+f"(c[1]), "+f"(c[2]), "+f"(c[3])
        : "r"(a0), "r"(a1), "r"(a2), "r"(a3), "r"(b0), "r"(b1));
}

__device__ __forceinline__ void ldsm_x4(uint32_t* r, uint32_t addr)
{
    asm volatile("ldmatrix.sync.aligned.m8n8.x4.shared.b16 {%0,%1,%2,%3}, [%4];"
                 : "=r"(r[0]), "=r"(r[1]), "=r"(r[2]), "=r"(r[3]) : "r"(addr));
}

__device__ __forceinline__ uint32_t pack_h2(float lo, float hi)
{
    __half2 h = __floats2half2_rn(lo, hi);
    return *(uint32_t*)&h;
}

__device__ __forceinline__ void cp_async16(uint32_t saddr, const void* g)
{
    asm volatile("cp.async.cg.shared.global [%0], [%1], 16;"
                 :: "r"(saddr), "l"(g));
}
#define CP_COMMIT() asm volatile("cp.async.commit_group;")
#define CP_WAIT(N)  asm volatile("cp.async.wait_group %0;" :: "n"(N))

// ---------------------------------------------------------------------------
// fp32 -> fp16 pre-rounding copy (optionally scaled)
// ---------------------------------------------------------------------------
__global__ void cvt_f16_kernel(const float* __restrict__ src,
                               __half* __restrict__ dst,
                               int n8, float scale)
{
    int i = blockIdx.x * 256 + threadIdx.x;
    if (i >= n8) return;
    float4 v0 = ((const float4*)src)[2 * i];
    float4 v1 = ((const float4*)src)[2 * i + 1];
    uint4 o;
    o.x = pack_h2(v0.x * scale, v0.y * scale);
    o.y = pack_h2(v0.z * scale, v0.w * scale);
    o.z = pack_h2(v1.x * scale, v1.y * scale);
    o.w = pack_h2(v1.z * scale, v1.w * scale);
    ((uint4*)dst)[i] = o;
}

// ---------------------------------------------------------------------------
// fp16 GEMM: CTA 128x128, 4 warps (2m x 2n), warp 64x64, BK=32, 3-stage
// cp.async, ldmatrix fragment loads. Smem rows 64B data + 16B pad (stride
// 40 halves = 20 banks -> conflict-free ldmatrix phases).
// ---------------------------------------------------------------------------
#define GK 2048
#define STAGE_B 10240                     // 128 rows * 80 bytes
#define GEMM_SMEM_BYTES (3 * 2 * STAGE_B) // 61440

template <bool TOHALF, bool HASBIAS>
__device__ __forceinline__ void gemm_f16_body(const __half* __restrict__ A,
                                              const __half* __restrict__ B,
                                              const float* __restrict__ bias,
                                              void* __restrict__ Cout)
{
    extern __shared__ __align__(16) char smem[];
    uint32_t sbase = (uint32_t)__cvta_generic_to_shared(smem);

    const int tid    = threadIdx.x;
    const int lane   = tid & 31;
    const int wid    = tid >> 5;
    const int warp_m = wid >> 1;
    const int warp_n = wid & 1;
    const int g      = lane >> 2;
    const int t      = lane & 3;
    const int bm     = blockIdx.y * 128;
    const int bn     = blockIdx.x * 128;

    // loader: row tr+32*it, 16B chunk tc
    const int tr = tid >> 2;              // 0..31
    const int tc = tid & 3;
    const __half* gA = A + (size_t)(bm + tr) * GK + tc * 8;
    const __half* gB = B + (size_t)(bn + tr) * GK + tc * 8;
    const uint32_t dst0 = tr * 80 + tc * 16;

    auto issue = [&](int stage) {
        uint32_t da = sbase + stage * STAGE_B + dst0;
        uint32_t db = da + 3 * STAGE_B;
#pragma unroll
        for (int it = 0; it < 4; it++)
            cp_async16(da + it * 32 * 80, gA + (size_t)it * 32 * GK);
#pragma unroll
        for (int it = 0; it < 4; it++)
            cp_async16(db + it * 32 * 80, gB + (size_t)it * 32 * GK);
        gA += 32;
        gB += 32;
        CP_COMMIT();
    };

    issue(0);
    issue(1);

    float acc[4][8][4];
#pragma unroll
    for (int mt = 0; mt < 4; mt++)
#pragma unroll
        for (int nt = 0; nt < 8; nt++)
#pragma unroll
            for (int i = 0; i < 4; i++) acc[mt][nt][i] = 0.f;

    // ldmatrix lane-address offsets (byte, within a stage)
    const uint32_t aoff =
        ((warp_m * 64 + (lane & 15)) * 40 + (lane >> 4) * 8) * 2;
    const uint32_t boff =
        ((warp_n * 64 + (lane & 7) + (lane >> 4) * 8) * 40 +
         ((lane >> 3) & 1) * 8) * 2;

    const int nk = GK / 32;   // 64
    for (int kt = 0; kt < nk; kt++) {
        if (kt < nk - 1) { CP_WAIT(1); } else { CP_WAIT(0); }
        __syncthreads();
        if (kt + 2 < nk) issue((kt + 2) % 3);

        const uint32_t sAst = sbase + (kt % 3) * STAGE_B;
        const uint32_t sBst = sAst + 3 * STAGE_B;

#pragma unroll
        for (int kg = 0; kg < 2; kg++) {
            uint32_t a[4][4], b[4][4];
#pragma unroll
            for (int mt = 0; mt < 4; mt++)
                ldsm_x4(a[mt], sAst + aoff + mt * 1280 + kg * 32);
#pragma unroll
            for (int p = 0; p < 4; p++)
                ldsm_x4(b[p], sBst + boff + p * 1280 + kg * 32);
#pragma unroll
            for (int mt = 0; mt < 4; mt++)
#pragma unroll
                for (int p = 0; p < 4; p++) {
                    mma_f16(acc[mt][2 * p], a[mt][0], a[mt][1], a[mt][2],
                            a[mt][3], b[p][0], b[p][1]);
                    mma_f16(acc[mt][2 * p + 1], a[mt][0], a[mt][1], a[mt][2],
                            a[mt][3], b[p][2], b[p][3]);
                }
        }
    }

#pragma unroll
    for (int mt = 0; mt < 4; mt++) {
        int row = bm + warp_m * 64 + mt * 16 + g;
#pragma unroll
        for (int nt = 0; nt < 8; nt++) {
            int col = bn + warp_n * 64 + nt * 8 + 2 * t;
            if (TOHALF) {
                __half* C = (__half*)Cout;
                *(__half2*)(C + (size_t)row * HDIM + col) =
                    __floats2half2_rn(acc[mt][nt][0], acc[mt][nt][1]);
                *(__half2*)(C + (size_t)(row + 8) * HDIM + col) =
                    __floats2half2_rn(acc[mt][nt][2], acc[mt][nt][3]);
            } else {
                float* C = (float*)Cout;
                float b0 = 0.f, b1 = 0.f;
                if (HASBIAS) { b0 = bias[col]; b1 = bias[col + 1]; }
                *(float2*)(C + (size_t)row * HDIM + col) =
                    make_float2(acc[mt][nt][0] + b0, acc[mt][nt][1] + b1);
                *(float2*)(C + (size_t)(row + 8) * HDIM + col) =
                    make_float2(acc[mt][nt][2] + b0, acc[mt][nt][3] + b1);
            }
        }
    }
}

__global__ void __launch_bounds__(128, 2) qkv_gemm_kernel()
{
    const __half* B = (blockIdx.z == 0) ? g_Wq : (blockIdx.z == 1) ? g_Wk : g_Wv;
    __half* C       = (blockIdx.z == 0) ? g_Q  : (blockIdx.z == 1) ? g_K  : g_V;
    gemm_f16_body<true, false>(g_X, B, nullptr, C);
}

__global__ void __launch_bounds__(128, 2) out_gemm_kernel(
    const float* __restrict__ bo, float* __restrict__ out)
{
    gemm_f16_body<false, true>(g_C, g_Wo, bo, out);
}

// ---------------------------------------------------------------------------
// RoPE in-place on g_Q, g_K
// ---------------------------------------------------------------------------
__global__ void rope_kernel(const int* __restrict__ pos_ids)
{
    int idx = blockIdx.x * 256 + threadIdx.x;
    if (idx >= MROWS * NH * 64) return;
    int d = idx & 63;
    int h = (idx >> 6) & 15;
    int m = idx >> 10;
    int s = m & (S_LEN - 1);

    float p = (float)pos_ids[s];
    float theta = expf(-0.14391156531392624f * (float)d);
    float ang = p * theta;
    float sn, cs;
    sincosf(ang, &sn, &cs);

    size_t base = (size_t)m * HDIM + h * DH + d;
    float q1 = __half2float(g_Q[base]), q2 = __half2float(g_Q[base + 64]);
    g_Q[base]      = __float2half_rn(q1 * cs - q2 * sn);
    g_Q[base + 64] = __float2half_rn(q1 * sn + q2 * cs);
    float k1 = __half2float(g_K[base]), k2 = __half2float(g_K[base + 64]);
    g_K[base]      = __float2half_rn(k1 * cs - k2 * sn);
    g_K[base + 64] = __float2half_rn(k1 * sn + k2 * cs);
}

// ---------------------------------------------------------------------------
// fp16 flash attention with ldmatrix fragment loads.
// CTA: 128 q x 64 kv, 8 warps. Qs[128][136], Ks[64][136], Vt[128][72].
// ---------------------------------------------------------------------------
#define QSTR 136
#define KSTR 136
#define VSTR 72
#define ATT_SMEM_BYTES ((128 * QSTR + 64 * KSTR + 128 * VSTR) * 2)

__global__ void __launch_bounds__(256) attn_kernel()
{
    extern __shared__ __align__(16) __half smh[];
    __half* Qs = smh;
    __half* Ks = Qs + 128 * QSTR;
    __half* Vt = Ks + 64 * KSTR;

    const int tid  = threadIdx.x;
    const int lane = tid & 31;
    const int w    = tid >> 5;
    const int g    = lane >> 2;
    const int t    = lane & 3;
    const int qt   = (gridDim.x - 1) - blockIdx.x;
    const int h    = blockIdx.y;
    const int n    = blockIdx.z;
    const int q0   = qt * 128;

    const size_t rowbase = (size_t)n * S_LEN;
    const size_t hoff    = (size_t)h * DH;

    const uint32_t smb   = (uint32_t)__cvta_generic_to_shared(smh);
    const uint32_t ks_b  = smb + 128 * QSTR * 2;
    const uint32_t vt_b  = ks_b + 64 * KSTR * 2;

    // ldmatrix lane offsets (bytes)
    const uint32_t qoff =
        smb + ((w * 16 + (lane & 15)) * QSTR + (lane >> 4) * 8) * 2;
    const uint32_t koff =
        ks_b + (((lane & 7) + (lane >> 4) * 8) * KSTR +
                ((lane >> 3) & 1) * 8) * 2;
    const uint32_t voff =
        vt_b + (((lane & 7) + (lane >> 4) * 8) * VSTR +
                ((lane >> 3) & 1) * 8) * 2;

    // Load Q tile
#pragma unroll
    for (int it = 0; it < 8; it++) {
        int id = tid + it * 256;
        int r  = id >> 4;
        int c  = id & 15;
        *(uint4*)&Qs[r * QSTR + c * 8] =
            *(const uint4*)(g_Q + (rowbase + q0 + r) * HDIM + hoff + c * 8);
    }

    float o[16][4];
#pragma unroll
    for (int dd = 0; dd < 16; dd++)
#pragma unroll
        for (int i = 0; i < 4; i++) o[dd][i] = 0.f;
    float m0 = -1e30f, m1 = -1e30f, l0 = 0.f, l1 = 0.f;

    const int row0 = q0 + w * 16 + g;
    const int nkt  = 2 * (qt + 1);

    for (int kt = 0; kt < nkt; kt++) {
        __syncthreads();
        const int k0 = kt * 64;
#pragma unroll
        for (int it = 0; it < 4; it++) {
            int id = tid + it * 256;
            int r  = id >> 4;
            int c  = id & 15;
            size_t gg = (rowbase + k0 + r) * HDIM + hoff + c * 8;
            *(uint4*)&Ks[r * KSTR + c * 8] = *(const uint4*)(g_K + gg);
            uint4 vv = *(const uint4*)(g_V + gg);
            const __half* vh = (const __half*)&vv;
#pragma unroll
            for (int j = 0; j < 8; j++)
                Vt[(c * 8 + j) * VSTR + r] = vh[j];
        }
        __syncthreads();

        // ---- S = Q K^T ----
        float s[8][4];
#pragma unroll
        for (int nn = 0; nn < 8; nn++)
#pragma unroll
            for (int i = 0; i < 4; i++) s[nn][i] = 0.f;

#pragma unroll
        for (int kg = 0; kg < 8; kg++) {
            uint32_t a[4];
            ldsm_x4(a, qoff + kg * 32);
#pragma unroll
            for (int p = 0; p < 4; p++) {
                uint32_t b[4];
                ldsm_x4(b, koff + p * (16 * KSTR * 2) + kg * 32);
                mma_f16(s[2 * p],     a[0], a[1], a[2], a[3], b[0], b[1]);
                mma_f16(s[2 * p + 1], a[0], a[1], a[2], a[3], b[2], b[3]);
            }
        }

        // ---- causal mask ----
        if (k0 + 63 > row0) {
#pragma unroll
            for (int nn = 0; nn < 8; nn++) {
                int col = k0 + nn * 8 + 2 * t;
                if (col > row0)     s[nn][0] = -1e30f;
                if (col + 1 > row0) s[nn][1] = -1e30f;
                if (col > row0 + 8)     s[nn][2] = -1e30f;
                if (col + 1 > row0 + 8) s[nn][3] = -1e30f;
            }
        }

        // ---- online softmax ----
        float mx0 = -1e30f, mx1 = -1e30f;
#pragma unroll
        for (int nn = 0; nn < 8; nn++) {
            mx0 = fmaxf(mx0, fmaxf(s[nn][0], s[nn][1]));
            mx1 = fmaxf(mx1, fmaxf(s[nn][2], s[nn][3]));
        }
        mx0 = fmaxf(mx0, __shfl_xor_sync(0xffffffffu, mx0, 1));
        mx0 = fmaxf(mx0, __shfl_xor_sync(0xffffffffu, mx0, 2));
        mx1 = fmaxf(mx1, __shfl_xor_sync(0xffffffffu, mx1, 1));
        mx1 = fmaxf(mx1, __shfl_xor_sync(0xffffffffu, mx1, 2));

        float newm0 = fmaxf(m0, mx0);
        float newm1 = fmaxf(m1, mx1);
        float alpha0 = __expf(m0 - newm0);
        float alpha1 = __expf(m1 - newm1);
        m0 = newm0; m1 = newm1;

        float sum0 = 0.f, sum1 = 0.f;
#pragma unroll
        for (int nn = 0; nn < 8; nn++) {
            s[nn][0] = __expf(s[nn][0] - newm0);
            s[nn][1] = __expf(s[nn][1] - newm0);
            s[nn][2] = __expf(s[nn][2] - newm1);
            s[nn][3] = __expf(s[nn][3] - newm1);
            sum0 += s[nn][0] + s[nn][1];
            sum1 += s[nn][2] + s[nn][3];
        }
        sum0 += __shfl_xor_sync(0xffffffffu, sum0, 1);
        sum0 += __shfl_xor_sync(0xffffffffu, sum0, 2);
        sum1 += __shfl_xor_sync(0xffffffffu, sum1, 1);
        sum1 += __shfl_xor_sync(0xffffffffu, sum1, 2);
        l0 = l0 * alpha0 + sum0;
        l1 = l1 * alpha1 + sum1;

#pragma unroll
        for (int dd = 0; dd < 16; dd++) {
            o[dd][0] *= alpha0; o[dd][1] *= alpha0;
            o[dd][2] *= alpha1; o[dd][3] *= alpha1;
        }

        // ---- O += P V ----
#pragma unroll
        for (int kg = 0; kg < 4; kg++) {
            uint32_t a0 = pack_h2(s[2 * kg][0],     s[2 * kg][1]);
            uint32_t a1 = pack_h2(s[2 * kg][2],     s[2 * kg][3]);
            uint32_t a2 = pack_h2(s[2 * kg + 1][0], s[2 * kg + 1][1]);
            uint32_t a3 = pack_h2(s[2 * kg + 1][2], s[2 * kg + 1][3]);
#pragma unroll
            for (int p = 0; p < 8; p++) {
                uint32_t b[4];
                ldsm_x4(b, voff + p * (16 * VSTR * 2) + kg * 32);
                mma_f16(o[2 * p],     a0, a1, a2, a3, b[0], b[1]);
                mma_f16(o[2 * p + 1], a0, a1, a2, a3, b[2], b[3]);
            }
        }
    }

    // ---- epilogue ----
    float inv0 = 1.f / l0;
    float inv1 = 1.f / l1;
    size_t r0 = (rowbase + row0) * HDIM + hoff;
    size_t r1 = r0 + 8 * HDIM;
#pragma unroll
    for (int dd = 0; dd < 16; dd++) {
        int col = dd * 8 + 2 * t;
        *(__half2*)(g_C + r0 + col) =
            __floats2half2_rn(o[dd][0] * inv0, o[dd][1] * inv0);
        *(__half2*)(g_C + r1 + col) =
            __floats2half2_rn(o[dd][2] * inv1, o[dd][3] * inv1);
    }
}

// ---------------------------------------------------------------------------
// kernel_launch
// Inputs: 0=X 1=position_ids 2=mask(unused,causal) 3=Wq 4=Wk 5=Wv 6=Wo 7=bo
// ---------------------------------------------------------------------------
extern "C" void kernel_launch(void* const* d_in, const int* in_sizes, int n_in,
                              void* d_out, int out_size)
{
    const float* X   = (const float*)d_in[0];
    const int*   pos = (const int*)d_in[1];
    const float* Wq  = (const float*)d_in[3];
    const float* Wk  = (const float*)d_in[4];
    const float* Wv  = (const float*)d_in[5];
    const float* Wo  = (const float*)d_in[6];
    const float* bo  = (const float*)d_in[7];
    float* out = (float*)d_out;

    cudaFuncSetAttribute(qkv_gemm_kernel,
                         cudaFuncAttributeMaxDynamicSharedMemorySize,
                         GEMM_SMEM_BYTES);
    cudaFuncSetAttribute(out_gemm_kernel,
                         cudaFuncAttributeMaxDynamicSharedMemorySize,
                         GEMM_SMEM_BYTES);
    cudaFuncSetAttribute(attn_kernel,
                         cudaFuncAttributeMaxDynamicSharedMemorySize,
                         ATT_SMEM_BYTES);

    __half *dX, *dWq, *dWk, *dWv, *dWo;
    cudaGetSymbolAddress((void**)&dX,  g_X);
    cudaGetSymbolAddress((void**)&dWq, g_Wq);
    cudaGetSymbolAddress((void**)&dWk, g_Wk);
    cudaGetSymbolAddress((void**)&dWv, g_Wv);
    cudaGetSymbolAddress((void**)&dWo, g_Wo);

    const float rs = 0.08838834764831845f;   // 1/sqrt(128)
    int nx8 = MROWS * HDIM / 8;
    int nw8 = HDIM * HDIM / 8;
    cvt_f16_kernel<<<nx8 / 256, 256>>>(X,  dX,  nx8, 1.f);
    cvt_f16_kernel<<<nw8 / 256, 256>>>(Wq, dWq, nw8, rs);
    cvt_f16_kernel<<<nw8 / 256, 256>>>(Wk, dWk, nw8, 1.f);
    cvt_f16_kernel<<<nw8 / 256, 256>>>(Wv, dWv, nw8, 1.f);
    cvt_f16_kernel<<<nw8 / 256, 256>>>(Wo, dWo, nw8, 1.f);

    dim3 g_qkv(HDIM / 128, MROWS / 128, 3);
    qkv_gemm_kernel<<<g_qkv, 128, GEMM_SMEM_BYTES>>>();

    int rope_threads = MROWS * NH * 64;
    rope_kernel<<<(rope_threads + 255) / 256, 256>>>(pos);

    dim3 g_att(S_LEN / 128, NH, NB);
    attn_kernel<<<g_att, 256, ATT_SMEM_BYTES>>>();

    dim3 g_out(HDIM / 128, MROWS / 128);
    out_gemm_kernel<<<g_out, 128, GEMM_SMEM_BYTES>>>(bo, out);
}

// round 11
// speedup vs baseline: 1.8113x; 1.2401x over previous
#include <cuda_runtime.h>
#include <cuda_fp16.h>
#include <math.h>
#include <stdint.h>

#define S_LEN 2048
#define HDIM  2048
#define NB    2
#define NH    16
#define DH    128
#define MROWS (NB * S_LEN)   // 4096

__device__ __half g_Q[MROWS * HDIM];
__device__ __half g_K[MROWS * HDIM];
__device__ __half g_V[MROWS * HDIM];
__device__ __half g_C[MROWS * HDIM];
__device__ __half g_X[MROWS * HDIM];
__device__ __half g_Wq[HDIM * HDIM];         // pre-scaled 1/sqrt(dh)
__device__ __half g_Wk[HDIM * HDIM];
__device__ __half g_Wv[HDIM * HDIM];
__device__ __half g_Wo[HDIM * HDIM];

// ---------------------------------------------------------------------------
// fp16 MMA m16n8k16 + ldmatrix helpers
// ---------------------------------------------------------------------------
__device__ __forceinline__ void mma_f16(float* c, uint32_t a0, uint32_t a1,
                                        uint32_t a2, uint32_t a3,
                                        uint32_t b0, uint32_t b1)
{
    asm("mma.sync.aligned.m16n8k16.row.col.f32.f16.f16.f32 "
        "{%0,%1,%2,%3}, {%4,%5,%6,%7}, {%8,%9}, {%0,%1,%2,%3};"
        : "+f"(c[0]), "+f"(c[1]), "+f"(c[2]), "+f"(c[3])
        : "r"(a0), "r"(a1), "r"(a2), "r"(a3), "r"(b0), "r"(b1));
}

__device__ __forceinline__ void ldsm_x4(uint32_t* r, uint32_t addr)
{
    asm volatile("ldmatrix.sync.aligned.m8n8.x4.shared.b16 {%0,%1,%2,%3}, [%4];"
                 : "=r"(r[0]), "=r"(r[1]), "=r"(r[2]), "=r"(r[3]) : "r"(addr));
}

__device__ __forceinline__ void ldsm_x4_t(uint32_t* r, uint32_t addr)
{
    asm volatile(
        "ldmatrix.sync.aligned.m8n8.x4.trans.shared.b16 {%0,%1,%2,%3}, [%4];"
        : "=r"(r[0]), "=r"(r[1]), "=r"(r[2]), "=r"(r[3]) : "r"(addr));
}

__device__ __forceinline__ uint32_t pack_h2(float lo, float hi)
{
    __half2 h = __floats2half2_rn(lo, hi);
    return *(uint32_t*)&h;
}

__device__ __forceinline__ void cp_async16(uint32_t saddr, const void* g)
{
    asm volatile("cp.async.cg.shared.global [%0], [%1], 16;"
                 :: "r"(saddr), "l"(g));
}
#define CP_COMMIT() asm volatile("cp.async.commit_group;")
#define CP_WAIT(N)  asm volatile("cp.async.wait_group %0;" :: "n"(N))

// ---------------------------------------------------------------------------
// fp32 -> fp16 pre-rounding copy kernels
// ---------------------------------------------------------------------------
__global__ void cvt_x_kernel(const float* __restrict__ src,
                             __half* __restrict__ dst, int n8)
{
    int i = blockIdx.x * 256 + threadIdx.x;
    if (i >= n8) return;
    float4 v0 = ((const float4*)src)[2 * i];
    float4 v1 = ((const float4*)src)[2 * i + 1];
    uint4 o;
    o.x = pack_h2(v0.x, v0.y);
    o.y = pack_h2(v0.z, v0.w);
    o.z = pack_h2(v1.x, v1.y);
    o.w = pack_h2(v1.z, v1.w);
    ((uint4*)dst)[i] = o;
}

__global__ void cvt_w_kernel(const float* __restrict__ Wq,
                             const float* __restrict__ Wk,
                             const float* __restrict__ Wv,
                             const float* __restrict__ Wo,
                             __half* __restrict__ dWq,
                             __half* __restrict__ dWk,
                             __half* __restrict__ dWv,
                             __half* __restrict__ dWo,
                             int n8, float rs)
{
    int i = blockIdx.x * 256 + threadIdx.x;
    if (i >= n8) return;
    const float* src = (blockIdx.y == 0) ? Wq : (blockIdx.y == 1) ? Wk
                     : (blockIdx.y == 2) ? Wv : Wo;
    __half* dst = (blockIdx.y == 0) ? dWq : (blockIdx.y == 1) ? dWk
                : (blockIdx.y == 2) ? dWv : dWo;
    float scale = (blockIdx.y == 0) ? rs : 1.f;
    float4 v0 = ((const float4*)src)[2 * i];
    float4 v1 = ((const float4*)src)[2 * i + 1];
    uint4 o;
    o.x = pack_h2(v0.x * scale, v0.y * scale);
    o.y = pack_h2(v0.z * scale, v0.w * scale);
    o.z = pack_h2(v1.x * scale, v1.y * scale);
    o.w = pack_h2(v1.z * scale, v1.w * scale);
    ((uint4*)dst)[i] = o;
}

// ---------------------------------------------------------------------------
// fp16 GEMM (unchanged from R10): CTA 128x128, 4 warps, BK=32, 3-stage
// cp.async, ldmatrix fragment loads, rows padded to 80B.
// ---------------------------------------------------------------------------
#define GK 2048
#define STAGE_B 10240                     // 128 rows * 80 bytes
#define GEMM_SMEM_BYTES (3 * 2 * STAGE_B) // 61440

template <bool TOHALF, bool HASBIAS>
__device__ __forceinline__ void gemm_f16_body(const __half* __restrict__ A,
                                              const __half* __restrict__ B,
                                              const float* __restrict__ bias,
                                              void* __restrict__ Cout)
{
    extern __shared__ __align__(16) char smem[];
    uint32_t sbase = (uint32_t)__cvta_generic_to_shared(smem);

    const int tid    = threadIdx.x;
    const int lane   = tid & 31;
    const int wid    = tid >> 5;
    const int warp_m = wid >> 1;
    const int warp_n = wid & 1;
    const int g      = lane >> 2;
    const int t      = lane & 3;
    const int bm     = blockIdx.y * 128;
    const int bn     = blockIdx.x * 128;

    const int tr = tid >> 2;
    const int tc = tid & 3;
    const __half* gA = A + (size_t)(bm + tr) * GK + tc * 8;
    const __half* gB = B + (size_t)(bn + tr) * GK + tc * 8;
    const uint32_t dst0 = tr * 80 + tc * 16;

    auto issue = [&](int stage) {
        uint32_t da = sbase + stage * STAGE_B + dst0;
        uint32_t db = da + 3 * STAGE_B;
#pragma unroll
        for (int it = 0; it < 4; it++)
            cp_async16(da + it * 32 * 80, gA + (size_t)it * 32 * GK);
#pragma unroll
        for (int it = 0; it < 4; it++)
            cp_async16(db + it * 32 * 80, gB + (size_t)it * 32 * GK);
        gA += 32;
        gB += 32;
        CP_COMMIT();
    };

    issue(0);
    issue(1);

    float acc[4][8][4];
#pragma unroll
    for (int mt = 0; mt < 4; mt++)
#pragma unroll
        for (int nt = 0; nt < 8; nt++)
#pragma unroll
            for (int i = 0; i < 4; i++) acc[mt][nt][i] = 0.f;

    const uint32_t aoff =
        ((warp_m * 64 + (lane & 15)) * 40 + (lane >> 4) * 8) * 2;
    const uint32_t boff =
        ((warp_n * 64 + (lane & 7) + (lane >> 4) * 8) * 40 +
         ((lane >> 3) & 1) * 8) * 2;

    const int nk = GK / 32;
    for (int kt = 0; kt < nk; kt++) {
        if (kt < nk - 1) { CP_WAIT(1); } else { CP_WAIT(0); }
        __syncthreads();
        if (kt + 2 < nk) issue((kt + 2) % 3);

        const uint32_t sAst = sbase + (kt % 3) * STAGE_B;
        const uint32_t sBst = sAst + 3 * STAGE_B;

#pragma unroll
        for (int kg = 0; kg < 2; kg++) {
            uint32_t a[4][4], b[4][4];
#pragma unroll
            for (int mt = 0; mt < 4; mt++)
                ldsm_x4(a[mt], sAst + aoff + mt * 1280 + kg * 32);
#pragma unroll
            for (int p = 0; p < 4; p++)
                ldsm_x4(b[p], sBst + boff + p * 1280 + kg * 32);
#pragma unroll
            for (int mt = 0; mt < 4; mt++)
#pragma unroll
                for (int p = 0; p < 4; p++) {
                    mma_f16(acc[mt][2 * p], a[mt][0], a[mt][1], a[mt][2],
                            a[mt][3], b[p][0], b[p][1]);
                    mma_f16(acc[mt][2 * p + 1], a[mt][0], a[mt][1], a[mt][2],
                            a[mt][3], b[p][2], b[p][3]);
                }
        }
    }

#pragma unroll
    for (int mt = 0; mt < 4; mt++) {
        int row = bm + warp_m * 64 + mt * 16 + g;
#pragma unroll
        for (int nt = 0; nt < 8; nt++) {
            int col = bn + warp_n * 64 + nt * 8 + 2 * t;
            if (TOHALF) {
                __half* C = (__half*)Cout;
                *(__half2*)(C + (size_t)row * HDIM + col) =
                    __floats2half2_rn(acc[mt][nt][0], acc[mt][nt][1]);
                *(__half2*)(C + (size_t)(row + 8) * HDIM + col) =
                    __floats2half2_rn(acc[mt][nt][2], acc[mt][nt][3]);
            } else {
                float* C = (float*)Cout;
                float b0 = 0.f, b1 = 0.f;
                if (HASBIAS) { b0 = bias[col]; b1 = bias[col + 1]; }
                *(float2*)(C + (size_t)row * HDIM + col) =
                    make_float2(acc[mt][nt][0] + b0, acc[mt][nt][1] + b1);
                *(float2*)(C + (size_t)(row + 8) * HDIM + col) =
                    make_float2(acc[mt][nt][2] + b0, acc[mt][nt][3] + b1);
            }
        }
    }
}

__global__ void __launch_bounds__(128, 2) qkv_gemm_kernel()
{
    const __half* B = (blockIdx.z == 0) ? g_Wq : (blockIdx.z == 1) ? g_Wk : g_Wv;
    __half* C       = (blockIdx.z == 0) ? g_Q  : (blockIdx.z == 1) ? g_K  : g_V;
    gemm_f16_body<true, false>(g_X, B, nullptr, C);
}

__global__ void __launch_bounds__(128, 2) out_gemm_kernel(
    const float* __restrict__ bo, float* __restrict__ out)
{
    gemm_f16_body<false, true>(g_C, g_Wo, bo, out);
}

// ---------------------------------------------------------------------------
// RoPE in-place on g_Q, g_K
// ---------------------------------------------------------------------------
__global__ void rope_kernel(const int* __restrict__ pos_ids)
{
    int idx = blockIdx.x * 256 + threadIdx.x;
    if (idx >= MROWS * NH * 64) return;
    int d = idx & 63;
    int h = (idx >> 6) & 15;
    int m = idx >> 10;
    int s = m & (S_LEN - 1);

    float p = (float)pos_ids[s];
    float theta = expf(-0.14391156531392624f * (float)d);
    float ang = p * theta;
    float sn, cs;
    sincosf(ang, &sn, &cs);

    size_t base = (size_t)m * HDIM + h * DH + d;
    float q1 = __half2float(g_Q[base]), q2 = __half2float(g_Q[base + 64]);
    g_Q[base]      = __float2half_rn(q1 * cs - q2 * sn);
    g_Q[base + 64] = __float2half_rn(q1 * sn + q2 * cs);
    float k1 = __half2float(g_K[base]), k2 = __half2float(g_K[base + 64]);
    g_K[base]      = __float2half_rn(k1 * cs - k2 * sn);
    g_K[base + 64] = __float2half_rn(k1 * sn + k2 * cs);
}

// ---------------------------------------------------------------------------
// fp16 flash attention v2: cp.async double-buffered K/V, V in natural
// [kv][d] layout consumed via ldmatrix.trans (no scalar transpose).
// CTA: 128 q x 64 kv, 8 warps. Strides 136 halves (conflict-free LDSM).
// Smem: Q[128][136] + 2 stages x (K[64][136] + V[64][136]) = 102 KB.
// ---------------------------------------------------------------------------
#define ASTR 136
#define QB   (128 * ASTR * 2)            // 34816 bytes
#define KVST (64 * ASTR * 2)             // 17408 bytes per K or V stage
#define ATT_SMEM_BYTES (QB + 2 * 2 * KVST)   // 104448

__global__ void __launch_bounds__(256, 2) attn_kernel()
{
    extern __shared__ __align__(16) __half smh[];
    __half* Qs = smh;

    const int tid  = threadIdx.x;
    const int lane = tid & 31;
    const int w    = tid >> 5;
    const int g    = lane >> 2;
    const int t    = lane & 3;
    const int qt   = (gridDim.x - 1) - blockIdx.x;   // heavy tiles first
    const int h    = blockIdx.y;
    const int n    = blockIdx.z;
    const int q0   = qt * 128;

    const size_t rowbase = (size_t)n * S_LEN;
    const size_t hoff    = (size_t)h * DH;

    const uint32_t smb = (uint32_t)__cvta_generic_to_shared(smh);

    // ldmatrix lane offsets (bytes, relative to tile bases)
    const uint32_t qoff =
        smb + ((w * 16 + (lane & 15)) * ASTR + (lane >> 4) * 8) * 2;
    const uint32_t koff =
        (((lane & 7) + (lane >> 4) * 8) * ASTR + ((lane >> 3) & 1) * 8) * 2;
    const uint32_t voff =
        ((lane & 15) * ASTR + (lane >> 4) * 8) * 2;

    // K/V tile loader via cp.async: 64 rows x 16 chunks of 16B, K then V
    const int lr = tid >> 2;              // 0..63 (row)  [4 chunks/thread/row]
    const int lc = tid & 3;               // chunk group
    auto loadkv = [&](int st, int kt) {
        int k0 = kt * 64;
        uint32_t kb = smb + QB + st * (2 * KVST);
        uint32_t vb = kb + KVST;
#pragma unroll
        for (int it = 0; it < 4; it++) {
            int c = lc * 4 + it;          // 0..15
            size_t gg = (rowbase + k0 + lr) * HDIM + hoff + c * 8;
            cp_async16(kb + (lr * ASTR + c * 8) * 2, g_K + gg);
            cp_async16(vb + (lr * ASTR + c * 8) * 2, g_V + gg);
        }
        CP_COMMIT();
    };

    // Load Q tile (plain)
#pragma unroll
    for (int it = 0; it < 8; it++) {
        int id = tid + it * 256;
        int r  = id >> 4;
        int c  = id & 15;
        *(uint4*)&Qs[r * ASTR + c * 8] =
            *(const uint4*)(g_Q + (rowbase + q0 + r) * HDIM + hoff + c * 8);
    }

    float o[16][4];
#pragma unroll
    for (int dd = 0; dd < 16; dd++)
#pragma unroll
        for (int i = 0; i < 4; i++) o[dd][i] = 0.f;
    float m0 = -1e30f, m1 = -1e30f, l0 = 0.f, l1 = 0.f;

    const int row0 = q0 + w * 16 + g;
    const int nkt  = 2 * (qt + 1);

    loadkv(0, 0);

    for (int kt = 0; kt < nkt; kt++) {
        const int st = kt & 1;
        if (kt + 1 < nkt) {
            loadkv(st ^ 1, kt + 1);
            CP_WAIT(1);
        } else {
            CP_WAIT(0);
        }
        __syncthreads();

        const uint32_t kb = smb + QB + st * (2 * KVST);
        const uint32_t vb = kb + KVST;
        const int k0 = kt * 64;

        // ---- S = Q K^T ----
        float s[8][4];
#pragma unroll
        for (int nn = 0; nn < 8; nn++)
#pragma unroll
            for (int i = 0; i < 4; i++) s[nn][i] = 0.f;

#pragma unroll
        for (int kg = 0; kg < 8; kg++) {
            uint32_t a[4];
            ldsm_x4(a, qoff + kg * 32);
#pragma unroll
            for (int p = 0; p < 4; p++) {
                uint32_t b[4];
                ldsm_x4(b, kb + koff + p * (16 * ASTR * 2) + kg * 32);
                mma_f16(s[2 * p],     a[0], a[1], a[2], a[3], b[0], b[1]);
                mma_f16(s[2 * p + 1], a[0], a[1], a[2], a[3], b[2], b[3]);
            }
        }

        // ---- causal mask ----
        if (k0 + 63 > row0) {
#pragma unroll
            for (int nn = 0; nn < 8; nn++) {
                int col = k0 + nn * 8 + 2 * t;
                if (col > row0)     s[nn][0] = -1e30f;
                if (col + 1 > row0) s[nn][1] = -1e30f;
                if (col > row0 + 8)     s[nn][2] = -1e30f;
                if (col + 1 > row0 + 8) s[nn][3] = -1e30f;
            }
        }

        // ---- online softmax ----
        float mx0 = -1e30f, mx1 = -1e30f;
#pragma unroll
        for (int nn = 0; nn < 8; nn++) {
            mx0 = fmaxf(mx0, fmaxf(s[nn][0], s[nn][1]));
            mx1 = fmaxf(mx1, fmaxf(s[nn][2], s[nn][3]));
        }
        mx0 = fmaxf(mx0, __shfl_xor_sync(0xffffffffu, mx0, 1));
        mx0 = fmaxf(mx0, __shfl_xor_sync(0xffffffffu, mx0, 2));
        mx1 = fmaxf(mx1, __shfl_xor_sync(0xffffffffu, mx1, 1));
        mx1 = fmaxf(mx1, __shfl_xor_sync(0xffffffffu, mx1, 2));

        float newm0 = fmaxf(m0, mx0);
        float newm1 = fmaxf(m1, mx1);
        float alpha0 = __expf(m0 - newm0);
        float alpha1 = __expf(m1 - newm1);
        m0 = newm0; m1 = newm1;

        float sum0 = 0.f, sum1 = 0.f;
#pragma unroll
        for (int nn = 0; nn < 8; nn++) {
            s[nn][0] = __expf(s[nn][0] - newm0);
            s[nn][1] = __expf(s[nn][1] - newm0);
            s[nn][2] = __expf(s[nn][2] - newm1);
            s[nn][3] = __expf(s[nn][3] - newm1);
            sum0 += s[nn][0] + s[nn][1];
            sum1 += s[nn][2] + s[nn][3];
        }
        sum0 += __shfl_xor_sync(0xffffffffu, sum0, 1);
        sum0 += __shfl_xor_sync(0xffffffffu, sum0, 2);
        sum1 += __shfl_xor_sync(0xffffffffu, sum1, 1);
        sum1 += __shfl_xor_sync(0xffffffffu, sum1, 2);
        l0 = l0 * alpha0 + sum0;
        l1 = l1 * alpha1 + sum1;

#pragma unroll
        for (int dd = 0; dd < 16; dd++) {
            o[dd][0] *= alpha0; o[dd][1] *= alpha0;
            o[dd][2] *= alpha1; o[dd][3] *= alpha1;
        }

        // ---- O += P V : V via ldmatrix.trans from natural layout ----
#pragma unroll
        for (int kg = 0; kg < 4; kg++) {
            uint32_t a0 = pack_h2(s[2 * kg][0],     s[2 * kg][1]);
            uint32_t a1 = pack_h2(s[2 * kg][2],     s[2 * kg][3]);
            uint32_t a2 = pack_h2(s[2 * kg + 1][0], s[2 * kg + 1][1]);
            uint32_t a3 = pack_h2(s[2 * kg + 1][2], s[2 * kg + 1][3]);
            const uint32_t vkg = vb + voff + kg * (16 * ASTR * 2);
#pragma unroll
            for (int p = 0; p < 8; p++) {
                uint32_t b[4];
                ldsm_x4_t(b, vkg + p * 32);
                mma_f16(o[2 * p],     a0, a1, a2, a3, b[0], b[1]);
                mma_f16(o[2 * p + 1], a0, a1, a2, a3, b[2], b[3]);
            }
        }
        __syncthreads();   // stage reusable for prefetch issued next iteration
    }

    // ---- epilogue ----
    float inv0 = 1.f / l0;
    float inv1 = 1.f / l1;
    size_t r0 = (rowbase + row0) * HDIM + hoff;
    size_t r1 = r0 + 8 * HDIM;
#pragma unroll
    for (int dd = 0; dd < 16; dd++) {
        int col = dd * 8 + 2 * t;
        *(__half2*)(g_C + r0 + col) =
            __floats2half2_rn(o[dd][0] * inv0, o[dd][1] * inv0);
        *(__half2*)(g_C + r1 + col) =
            __floats2half2_rn(o[dd][2] * inv1, o[dd][3] * inv1);
    }
}

// ---------------------------------------------------------------------------
// kernel_launch
// Inputs: 0=X 1=position_ids 2=mask(unused,causal) 3=Wq 4=Wk 5=Wv 6=Wo 7=bo
// ---------------------------------------------------------------------------
extern "C" void kernel_launch(void* const* d_in, const int* in_sizes, int n_in,
                              void* d_out, int out_size)
{
    const float* X   = (const float*)d_in[0];
    const int*   pos = (const int*)d_in[1];
    const float* Wq  = (const float*)d_in[3];
    const float* Wk  = (const float*)d_in[4];
    const float* Wv  = (const float*)d_in[5];
    const float* Wo  = (const float*)d_in[6];
    const float* bo  = (const float*)d_in[7];
    float* out = (float*)d_out;

    cudaFuncSetAttribute(qkv_gemm_kernel,
                         cudaFuncAttributeMaxDynamicSharedMemorySize,
                         GEMM_SMEM_BYTES);
    cudaFuncSetAttribute(out_gemm_kernel,
                         cudaFuncAttributeMaxDynamicSharedMemorySize,
                         GEMM_SMEM_BYTES);
    cudaFuncSetAttribute(attn_kernel,
                         cudaFuncAttributeMaxDynamicSharedMemorySize,
                         ATT_SMEM_BYTES);

    __half *dX, *dWq, *dWk, *dWv, *dWo;
    cudaGetSymbolAddress((void**)&dX,  g_X);
    cudaGetSymbolAddress((void**)&dWq, g_Wq);
    cudaGetSymbolAddress((void**)&dWk, g_Wk);
    cudaGetSymbolAddress((void**)&dWv, g_Wv);
    cudaGetSymbolAddress((void**)&dWo, g_Wo);

    const float rs = 0.08838834764831845f;   // 1/sqrt(128)
    int nx8 = MROWS * HDIM / 8;
    int nw8 = HDIM * HDIM / 8;
    cvt_x_kernel<<<nx8 / 256, 256>>>(X, dX, nx8);
    dim3 g_w(nw8 / 256, 4);
    cvt_w_kernel<<<g_w, 256>>>(Wq, Wk, Wv, Wo, dWq, dWk, dWv, dWo, nw8, rs);

    dim3 g_qkv(HDIM / 128, MROWS / 128, 3);
    qkv_gemm_kernel<<<g_qkv, 128, GEMM_SMEM_BYTES>>>();

    int rope_threads = MROWS * NH * 64;
    rope_kernel<<<(rope_threads + 255) / 256, 256>>>(pos);

    dim3 g_att(S_LEN / 128, NH, NB);
    attn_kernel<<<g_att, 256, ATT_SMEM_BYTES>>>();

    dim3 g_out(HDIM / 128, MROWS / 128);
    out_gemm_kernel<<<g_out, 128, GEMM_SMEM_BYTES>>>(bo, out);
}